// round 7
// baseline (speedup 1.0000x reference)
#include <cuda_runtime.h>
#include <cuda_fp16.h>
#include <math.h>
#include <stdint.h>

// Problem constants
#define T_LEN 512
#define NBATCH 64
#define HID 512
#define G4 2048          // 4*HID
#define NVOCAB 10000

#define SCAN_BLOCKS 128
#define SCAN_THREADS 128
#define RPAD 20          // red buffer row pad (floats)

// -------- device scratch --------
__device__ __align__(16) __half g_E0h[(size_t)NVOCAB * G4];     // emb @ Wih0^T + b0 (fp16, 40 MB)
__device__ float g_h1[(size_t)T_LEN * NBATCH * HID];            // layer0 outputs [t*64+b][u]
__device__ __align__(16) __half g_xW1h[(size_t)T_LEN * G4 * NBATCH]; // [t][r][b] fp16 (128 MB)
__device__ __align__(16) __half g_hbuf16[2][NBATCH * HID];      // ping-pong h, fragment layout
__device__ unsigned g_flags[SCAN_BLOCKS];                        // per-block step flags

// ---------------- helpers ----------------
__device__ __forceinline__ void mma_tf32(float* c, const unsigned* a, const unsigned* b) {
    asm("mma.sync.aligned.m16n8k8.row.col.f32.tf32.tf32.f32 "
        "{%0,%1,%2,%3}, {%4,%5,%6,%7}, {%8,%9}, {%0,%1,%2,%3};"
        : "+f"(c[0]), "+f"(c[1]), "+f"(c[2]), "+f"(c[3])
        : "r"(a[0]), "r"(a[1]), "r"(a[2]), "r"(a[3]), "r"(b[0]), "r"(b[1]));
}
__device__ __forceinline__ void mma_f16(float* c, const unsigned* a, const unsigned* b) {
    asm("mma.sync.aligned.m16n8k16.row.col.f32.f16.f16.f32 "
        "{%0,%1,%2,%3}, {%4,%5,%6,%7}, {%8,%9}, {%0,%1,%2,%3};"
        : "+f"(c[0]), "+f"(c[1]), "+f"(c[2]), "+f"(c[3])
        : "r"(a[0]), "r"(a[1]), "r"(a[2]), "r"(a[3]), "r"(b[0]), "r"(b[1]));
}
__device__ __forceinline__ unsigned ld_acq(const unsigned* p) {
    unsigned v; asm volatile("ld.acquire.gpu.global.u32 %0, [%1];" : "=r"(v) : "l"(p)); return v;
}
__device__ __forceinline__ void st_rel(unsigned* p, unsigned v) {
    asm volatile("st.release.gpu.global.u32 [%0], %1;" :: "l"(p), "r"(v));
}
__device__ __forceinline__ void cp16(unsigned sdst, const void* gsrc) {
    asm volatile("cp.async.cg.shared.global [%0], [%1], 16;" :: "r"(sdst), "l"(gsrc));
}
__device__ __forceinline__ float tanh_ap(float x) {
    float y; asm("tanh.approx.f32 %0, %1;" : "=f"(y) : "f"(x)); return y;
}
__device__ __forceinline__ float sig_(float x) {
    return __fdividef(1.0f, 1.0f + __expf(-x));
}
// fp16 half-index for h value (batch b, unit k) in m16n8k16 A-fragment layout.
__device__ __forceinline__ int hidx16(int b, int k) {
    int kk = k >> 4, mt = b >> 4, r = b & 15, kl = k & 15;
    int lane = (r & 7) * 4 + ((kl & 7) >> 1);
    int w = ((kl >> 3) << 1) | (r >> 3);
    return (((kk * 4 + mt) * 32 + lane) * 4 + w) * 2 + (k & 1);
}

// ---------------------------------------------------------------------------
__global__ void zero_init_kernel() {
    int i = blockIdx.x * blockDim.x + threadIdx.x;
    if (i < (NBATCH * HID) / 2) ((unsigned*)g_hbuf16)[i] = 0u;  // g_hbuf16[0]
    if (i < SCAN_BLOCKS) g_flags[i] = 0u;
}

// ---------------------------------------------------------------------------
// tf32 tensor-core GEMM: C = A[M][512] @ W[2048][512]^T + (b1+b2), fp16 out.
//   dst_sel 0: C = g_E0h, layout [m][2048]
//   dst_sel 1: C = g_xW1h, layout [t][r][b], m = t*64+b (smem-staged epilogue)
// ---------------------------------------------------------------------------
#define GSTR 36
#define GBUF (128 * GSTR)

__global__ __launch_bounds__(256) void gemm_tf32_kernel(
    const float* __restrict__ A_in,
    const float* __restrict__ W,
    const float* __restrict__ bi1,
    const float* __restrict__ bi2,
    int dst_sel, int M)
{
    const float* A = A_in ? A_in : g_h1;

    extern __shared__ unsigned gsm[];
    unsigned* As = gsm;
    unsigned* Bs = gsm + 2 * GBUF;

    const int tid = threadIdx.x;
    const int lane = tid & 31;
    const int warp = tid >> 5;
    const int g = lane >> 2;
    const int tig = lane & 3;
    const int wm = warp & 1;
    const int wn = warp >> 1;
    const int m0 = blockIdx.y * 128;
    const int n0 = blockIdx.x * 128;

    float acc[4][4][4];
#pragma unroll
    for (int i = 0; i < 4; i++)
#pragma unroll
        for (int j = 0; j < 4; j++)
#pragma unroll
            for (int e = 0; e < 4; e++) acc[i][j][e] = 0.0f;

    int lrow[4], lc[4];
#pragma unroll
    for (int p = 0; p < 4; p++) {
        int id = tid + p * 256;
        lrow[p] = id >> 3;
        lc[p] = (id & 7) * 4;
    }

    {
#pragma unroll
        for (int p = 0; p < 4; p++) {
            int r = lrow[p], kc = lc[p];
            float4 va = make_float4(0.f, 0.f, 0.f, 0.f);
            if (m0 + r < M) va = *(const float4*)(A + (size_t)(m0 + r) * 512 + kc);
            *(uint4*)(As + r * GSTR + kc) = *(const uint4*)&va;
            float4 vb = *(const float4*)(W + (size_t)(n0 + r) * 512 + kc);
            *(uint4*)(Bs + r * GSTR + kc) = *(const uint4*)&vb;
        }
    }
    __syncthreads();

    float4 pa[4], pb[4];
    for (int it = 0; it < 16; it++) {
        int buf = it & 1;
        if (it < 15) {
            int k0 = (it + 1) * 32;
#pragma unroll
            for (int p = 0; p < 4; p++) {
                int r = lrow[p], kc = lc[p];
                pa[p] = make_float4(0.f, 0.f, 0.f, 0.f);
                if (m0 + r < M) pa[p] = *(const float4*)(A + (size_t)(m0 + r) * 512 + k0 + kc);
                pb[p] = *(const float4*)(W + (size_t)(n0 + r) * 512 + k0 + kc);
            }
        }
        const unsigned* Ab = As + buf * GBUF;
        const unsigned* Bb = Bs + buf * GBUF;
#pragma unroll
        for (int kk = 0; kk < 4; kk++) {
            int kb = kk * 8;
            unsigned af[4][4];
#pragma unroll
            for (int mf = 0; mf < 4; mf++) {
                int r = wm * 64 + mf * 16 + g;
                af[mf][0] = Ab[r * GSTR + kb + tig];
                af[mf][1] = Ab[(r + 8) * GSTR + kb + tig];
                af[mf][2] = Ab[r * GSTR + kb + tig + 4];
                af[mf][3] = Ab[(r + 8) * GSTR + kb + tig + 4];
            }
            unsigned bf[4][2];
#pragma unroll
            for (int nf = 0; nf < 4; nf++) {
                int n = wn * 32 + nf * 8 + g;
                bf[nf][0] = Bb[n * GSTR + kb + tig];
                bf[nf][1] = Bb[n * GSTR + kb + tig + 4];
            }
#pragma unroll
            for (int mf = 0; mf < 4; mf++)
#pragma unroll
                for (int nf = 0; nf < 4; nf++)
                    mma_tf32(acc[mf][nf], af[mf], bf[nf]);
        }
        if (it < 15) {
            unsigned* Ad = As + (buf ^ 1) * GBUF;
            unsigned* Bd = Bs + (buf ^ 1) * GBUF;
#pragma unroll
            for (int p = 0; p < 4; p++) {
                int r = lrow[p], kc = lc[p];
                *(uint4*)(Ad + r * GSTR + kc) = *(const uint4*)&pa[p];
                *(uint4*)(Bd + r * GSTR + kc) = *(const uint4*)&pb[p];
            }
        }
        __syncthreads();
    }

    if (dst_sel) {
        // stage fp16 tile in smem as [t_loc][n_loc][b], then 2 linear 16KB stores
        __half* ep = (__half*)gsm;   // 16384 halfs = 32 KB (loop is done with gsm)
#pragma unroll
        for (int nf = 0; nf < 4; nf++) {
            int nl = wn * 32 + nf * 8 + 2 * tig;
            int n = n0 + nl;
            float bb0 = bi1[n] + bi2[n];
            float bb1 = bi1[n + 1] + bi2[n + 1];
#pragma unroll
            for (int mf = 0; mf < 4; mf++) {
                int m = wm * 64 + mf * 16 + g;       // local m
                int tl = m >> 6, b = m & 63;
                ep[tl * 8192 + nl * 64 + b]       = __float2half_rn(acc[mf][nf][0] + bb0);
                ep[tl * 8192 + (nl + 1) * 64 + b] = __float2half_rn(acc[mf][nf][1] + bb1);
                int m2 = m + 8;
                int tl2 = m2 >> 6, b2 = m2 & 63;
                ep[tl2 * 8192 + nl * 64 + b2]       = __float2half_rn(acc[mf][nf][2] + bb0);
                ep[tl2 * 8192 + (nl + 1) * 64 + b2] = __float2half_rn(acc[mf][nf][3] + bb1);
            }
        }
        __syncthreads();
        // copy out: [t0 + tl][n0*64 .. n0*64 + 8192) contiguous per tl
        size_t base = (size_t)(m0 >> 6) * (G4 * 64) + (size_t)n0 * 64;
#pragma unroll
        for (int i = 0; i < 8; i++) {
            int idx4 = tid + i * 256;            // uint4 index, 2048 total
            int tl = idx4 >> 10;                 // 1024 uint4 per tl
            int within = idx4 & 1023;
            uint4 v = *(const uint4*)(ep + idx4 * 8);
            *(uint4*)(g_xW1h + base + (size_t)tl * (G4 * 64) + within * 8) = v;
        }
    } else {
#pragma unroll
        for (int nf = 0; nf < 4; nf++) {
            int n = n0 + wn * 32 + nf * 8 + 2 * tig;
            float bb0 = bi1[n] + bi2[n];
            float bb1 = bi1[n + 1] + bi2[n + 1];
#pragma unroll
            for (int mf = 0; mf < 4; mf++) {
                int r = m0 + wm * 64 + mf * 16 + g;
                if (r < M) {
                    __half2 v = __floats2half2_rn(acc[mf][nf][0] + bb0, acc[mf][nf][1] + bb1);
                    *(__half2*)(g_E0h + (size_t)r * G4 + n) = v;
                }
                if (r + 8 < M) {
                    __half2 v = __floats2half2_rn(acc[mf][nf][2] + bb0, acc[mf][nf][3] + bb1);
                    *(__half2*)(g_E0h + (size_t)(r + 8) * G4 + n) = v;
                }
            }
        }
    }
}

// ---------------------------------------------------------------------------
// Persistent LSTM scan, fp16 h + m16n8k16 mma, distributed per-warp barrier.
// 128 CTAs x 128 threads flat (1/SM). Block owns 16 gate rows (4 units).
// Warp w owns K-slice [128w,128w+128), produced exactly by blocks [32w,32w+32):
//   - warp w polls flags[32w+lane] (coalesced ld.acquire + __all_sync), then
//     stages its 16KB slice via cp.async — no full-grid barrier on the
//     critical path; the 4 warps jointly cover all 128 flags before the
//     block-wide reduction sync, preserving 2-step buffer-reuse safety.
//   - block posts flags[bid]=t+1 (st.release) after its cell phase.
// ---------------------------------------------------------------------------
__global__ __launch_bounds__(SCAN_THREADS) void lstm_scan_kernel(
    const int* __restrict__ src,        // nullptr for layer 1
    const float* __restrict__ Whh,
    const int* __restrict__ sen_len,    // nullptr for layer 0
    float* __restrict__ final_out)      // nullptr for layer 0
{
    extern __shared__ unsigned ssm[];
    unsigned* sh_h = ssm;                          // 16384 u32 = 64KB fp16 h
    float* red = (float*)(ssm + 16384);            // [4][64][RPAD]
    float* hex = (float*)(ssm + 16384 + 4 * 64 * RPAD);  // [4][64]

    const int tid = threadIdx.x;
    const int lane = tid & 31;
    const int warp = tid >> 5;       // 0..3 = k-slice
    const int g = lane >> 2;
    const int tig = lane & 3;
    const int u0 = blockIdx.x * 4;
    const int b0 = lane, b1 = lane + 32;
    const int ug = warp;

    unsigned sh_base;
    asm("{ .reg .u64 t; cvta.to.shared.u64 t, %1; cvt.u32.u64 %0, t; }"
        : "=r"(sh_base) : "l"((void*)ssm));

    // ---- B (Whh) fp16 fragments in registers, once per scan ----
    unsigned breg[8][2][2];
#pragma unroll
    for (int kkl = 0; kkl < 8; kkl++) {
#pragma unroll
        for (int nt = 0; nt < 2; nt++) {
            int n = nt * 8 + g;
            int row = (n & 3) * 512 + u0 + (n >> 2);
            const float* wr = Whh + (size_t)row * 512 + warp * 128 + kkl * 16;
            __half2 h0 = __floats2half2_rn(wr[2 * tig], wr[2 * tig + 1]);
            __half2 h1 = __floats2half2_rn(wr[2 * tig + 8], wr[2 * tig + 9]);
            breg[kkl][nt][0] = *(unsigned*)&h0;
            breg[kkl][nt][1] = *(unsigned*)&h1;
        }
    }

    float c_0 = 0.0f, c_1 = 0.0f;
    int sl0 = -1, sl1 = -1;
    if (sen_len) { sl0 = sen_len[b0]; sl1 = sen_len[b1]; }

    const int u_cell = u0 + ug;
    const int hi0 = hidx16(b0, u_cell);
    const int hi1 = hidx16(b1, u_cell);
    const unsigned* myflag = &g_flags[warp * 32 + lane];

    for (int t = 0; t < T_LEN; t++) {
        // ---- per-warp wait: my slice's 32 producer blocks at step t ----
        unsigned want = (unsigned)t;
        while (!__all_sync(0xffffffffu, ld_acq(myflag) >= want)) { }

        // ---- stage this warp's k-slice of h (16 KB) via cp.async ----
        {
            const uint4* hs = (const uint4*)(g_hbuf16[t & 1]) + warp * 1024 + lane;
            unsigned sd = sh_base + (unsigned)(warp * 16384 + lane * 16);
#pragma unroll 8
            for (int i = 0; i < 32; i++)
                cp16(sd + i * 512, hs + i * 32);
            asm volatile("cp.async.commit_group;");
        }

        // ---- prefetch cell inputs (fp16, independent of h) ----
        float p0[4], p1[4];
        if (src) {
            int r0 = src[t * NBATCH + b0];
            int r1 = src[t * NBATCH + b1];
            const __half* e0 = g_E0h + (size_t)r0 * G4 + u0 + ug;
            const __half* e1 = g_E0h + (size_t)r1 * G4 + u0 + ug;
#pragma unroll
            for (int gt = 0; gt < 4; gt++) {
                p0[gt] = __half2float(e0[gt * 512]);
                p1[gt] = __half2float(e1[gt * 512]);
            }
        } else {
            const __half* xb = g_xW1h + (size_t)t * (G4 * 64) + (size_t)(u0 + ug) * 64;
#pragma unroll
            for (int gt = 0; gt < 4; gt++) {
                p0[gt] = __half2float(xb[gt * 32768 + b0]);
                p1[gt] = __half2float(xb[gt * 32768 + b1]);
            }
        }

        asm volatile("cp.async.wait_group 0;" ::: "memory");
        __syncwarp();

        // ---- mma: m64 x n16 x k128 partial (f16, fp32 acc) ----
        float acc[4][2][4];
#pragma unroll
        for (int mt = 0; mt < 4; mt++)
#pragma unroll
            for (int nt = 0; nt < 2; nt++)
#pragma unroll
                for (int e = 0; e < 4; e++) acc[mt][nt][e] = 0.0f;

#pragma unroll
        for (int kkl = 0; kkl < 8; kkl++) {
            int kkg = warp * 8 + kkl;
#pragma unroll
            for (int mt = 0; mt < 4; mt++) {
                uint4 a = *(const uint4*)(sh_h + ((kkg * 4 + mt) * 32 + lane) * 4);
                mma_f16(acc[mt][0], (const unsigned*)&a, breg[kkl][0]);
                mma_f16(acc[mt][1], (const unsigned*)&a, breg[kkl][1]);
            }
        }

        // ---- store partials: red[w][b][n] ----
#pragma unroll
        for (int mt = 0; mt < 4; mt++)
#pragma unroll
            for (int nt = 0; nt < 2; nt++) {
                int bb = mt * 16 + g;
                float* rp = &red[(warp * 64 + bb) * RPAD + nt * 8 + 2 * tig];
                *(float2*)rp = make_float2(acc[mt][nt][0], acc[mt][nt][1]);
                *(float2*)(rp + 8 * RPAD) = make_float2(acc[mt][nt][2], acc[mt][nt][3]);
            }
        __syncthreads();

        // ---- cell phase ----
        float z0[4], z1[4];
#pragma unroll
        for (int gt = 0; gt < 4; gt++) { z0[gt] = p0[gt]; z1[gt] = p1[gt]; }
#pragma unroll
        for (int w = 0; w < 4; w++) {
            float4 v0 = *(const float4*)&red[(w * 64 + b0) * RPAD + ug * 4];
            float4 v1 = *(const float4*)&red[(w * 64 + b1) * RPAD + ug * 4];
            z0[0] += v0.x; z0[1] += v0.y; z0[2] += v0.z; z0[3] += v0.w;
            z1[0] += v1.x; z1[1] += v1.y; z1[2] += v1.z; z1[3] += v1.w;
        }

        float i0 = sig_(z0[0]), f0 = sig_(z0[1]), gg0 = tanh_ap(z0[2]), o0 = sig_(z0[3]);
        c_0 = f0 * c_0 + i0 * gg0;
        float h0n = o0 * tanh_ap(c_0);

        float i1 = sig_(z1[0]), f1 = sig_(z1[1]), gg1 = tanh_ap(z1[2]), o1 = sig_(z1[3]);
        c_1 = f1 * c_1 + i1 * gg1;
        float h1n = o1 * tanh_ap(c_1);

        __half* hd = g_hbuf16[(t + 1) & 1];
        hd[hi0] = __float2half_rn(h0n);
        hd[hi1] = __float2half_rn(h1n);

        if (src) {
            hex[ug * 64 + b0] = h0n;
            hex[ug * 64 + b1] = h1n;
        } else {
            if (t == sl0 - 1) final_out[b0 * HID + u_cell] = h0n;
            if (t == sl1 - 1) final_out[b1 * HID + u_cell] = h1n;
        }

        // ---- publish: all h stores (cta-ordered by bar) then release flag ----
        __syncthreads();
        if (tid == 0) st_rel(&g_flags[blockIdx.x], (unsigned)(t + 1));
        if (src && tid < 64) {
            float4 v = make_float4(hex[tid], hex[64 + tid], hex[128 + tid], hex[192 + tid]);
            *(float4*)(g_h1 + (size_t)(t * NBATCH + tid) * HID + u0) = v;
        }
    }
}

// ---------------------------------------------------------------------------
extern "C" void kernel_launch(void* const* d_in, const int* in_sizes, int n_in,
                              void* d_out, int out_size)
{
    const int*   src       = (const int*)  d_in[0];
    const int*   sen_len   = (const int*)  d_in[1];
    const float* emb_table = (const float*)d_in[2];
    const float* Wih0      = (const float*)d_in[3];
    const float* Whh0      = (const float*)d_in[4];
    const float* bih0      = (const float*)d_in[5];
    const float* bhh0      = (const float*)d_in[6];
    const float* Wih1      = (const float*)d_in[7];
    const float* Whh1      = (const float*)d_in[8];
    const float* bih1      = (const float*)d_in[9];
    const float* bhh1      = (const float*)d_in[10];
    float* out = (float*)d_out;

    const size_t gemm_smem = (size_t)4 * GBUF * sizeof(unsigned);     // 73728 B
    const size_t scan_smem =
        (size_t)(16384 + 4 * 64 * RPAD + 256) * sizeof(unsigned);     // 87040 B
    cudaFuncSetAttribute(gemm_tf32_kernel,
                         cudaFuncAttributeMaxDynamicSharedMemorySize, (int)gemm_smem);
    cudaFuncSetAttribute(lstm_scan_kernel,
                         cudaFuncAttributeMaxDynamicSharedMemorySize, (int)scan_smem);

    // Phase 0: E0 = emb_table @ Wih0^T + b0   (10000 x 2048, fp16 out)
    {
        dim3 grid(G4 / 128, (NVOCAB + 127) / 128);
        gemm_tf32_kernel<<<grid, 256, gemm_smem>>>(emb_table, Wih0, bih0, bhh0, 0, NVOCAB);
    }

    // Phase 1: layer-0 scan
    zero_init_kernel<<<64, 512>>>();
    lstm_scan_kernel<<<SCAN_BLOCKS, SCAN_THREADS, scan_smem>>>(
        src, Whh0, nullptr, nullptr);

    // Phase 2: xW1 = h1 @ Wih1^T + b1  -> fp16 [t][r][b]
    {
        dim3 grid(G4 / 128, (T_LEN * NBATCH) / 128);
        gemm_tf32_kernel<<<grid, 256, gemm_smem>>>(nullptr, Wih1, bih1, bhh1, 1,
                                                   T_LEN * NBATCH);
    }

    // Phase 3: layer-1 scan (+ final gather at sen_len-1)
    zero_init_kernel<<<64, 512>>>();
    lstm_scan_kernel<<<SCAN_BLOCKS, SCAN_THREADS, scan_smem>>>(
        nullptr, Whh1, sen_len, out);
}

// round 8
// speedup vs baseline: 1.5669x; 1.5669x over previous
#include <cuda_runtime.h>
#include <cuda_fp16.h>
#include <math.h>
#include <stdint.h>

// Problem constants
#define T_LEN 512
#define NBATCH 64
#define HID 512
#define G4 2048          // 4*HID
#define NVOCAB 10000

#define SCAN_BLOCKS 64
#define SCAN_THREADS 256
#define RSTR 36          // red buffer row stride (floats)

// -------- device scratch --------
__device__ __align__(16) __half g_E0h[(size_t)NVOCAB * G4];     // emb @ Wih0^T + b0 (fp16)
__device__ float g_h1[(size_t)T_LEN * NBATCH * HID];            // layer0 outputs [t*64+b][u]
__device__ __align__(16) __half g_xW1h[(size_t)T_LEN * G4 * NBATCH]; // [t][r][b] fp16
__device__ __align__(16) __half g_hbuf16[2][NBATCH * HID];      // ping-pong h, fragment layout
__device__ unsigned g_ctr;                                       // barrier counter (monotonic)

// ---------------- helpers ----------------
__device__ __forceinline__ void mma_tf32(float* c, const unsigned* a, const unsigned* b) {
    asm("mma.sync.aligned.m16n8k8.row.col.f32.tf32.tf32.f32 "
        "{%0,%1,%2,%3}, {%4,%5,%6,%7}, {%8,%9}, {%0,%1,%2,%3};"
        : "+f"(c[0]), "+f"(c[1]), "+f"(c[2]), "+f"(c[3])
        : "r"(a[0]), "r"(a[1]), "r"(a[2]), "r"(a[3]), "r"(b[0]), "r"(b[1]));
}
__device__ __forceinline__ void mma_f16(float* c, const unsigned* a, const unsigned* b) {
    asm("mma.sync.aligned.m16n8k16.row.col.f32.f16.f16.f32 "
        "{%0,%1,%2,%3}, {%4,%5,%6,%7}, {%8,%9}, {%0,%1,%2,%3};"
        : "+f"(c[0]), "+f"(c[1]), "+f"(c[2]), "+f"(c[3])
        : "r"(a[0]), "r"(a[1]), "r"(a[2]), "r"(a[3]), "r"(b[0]), "r"(b[1]));
}
__device__ __forceinline__ unsigned ld_acq(const unsigned* p) {
    unsigned v; asm volatile("ld.acquire.gpu.global.u32 %0, [%1];" : "=r"(v) : "l"(p)); return v;
}
__device__ __forceinline__ void cp16(unsigned sdst, const void* gsrc) {
    asm volatile("cp.async.cg.shared.global [%0], [%1], 16;" :: "r"(sdst), "l"(gsrc));
}
__device__ __forceinline__ float tanh_ap(float x) {
    float y; asm("tanh.approx.f32 %0, %1;" : "=f"(y) : "f"(x)); return y;
}
__device__ __forceinline__ float sig_(float x) {
    return __fdividef(1.0f, 1.0f + __expf(-x));
}
// fp16 half-index for h value (batch b, unit k) in m16n8k16 A-fragment layout.
__device__ __forceinline__ int hidx16(int b, int k) {
    int kk = k >> 4, mt = b >> 4, r = b & 15, kl = k & 15;
    int lane = (r & 7) * 4 + ((kl & 7) >> 1);
    int w = ((kl >> 3) << 1) | (r >> 3);
    return (((kk * 4 + mt) * 32 + lane) * 4 + w) * 2 + (k & 1);
}

// ---------------------------------------------------------------------------
__global__ void zero_init_kernel() {
    int i = blockIdx.x * blockDim.x + threadIdx.x;
    if (i < (NBATCH * HID) / 2) ((unsigned*)g_hbuf16)[i] = 0u;  // g_hbuf16[0]
    if (i == 0) g_ctr = 0u;
}

// ---------------------------------------------------------------------------
// tf32 tensor-core GEMM: C = A[M][512] @ W[2048][512]^T + (b1+b2), fp16 out.
//   dst_sel 0: C = g_E0h, layout [m][2048]
//   dst_sel 1: C = g_xW1h, layout [t][r][b], m = t*64+b (smem-staged epilogue)
// ---------------------------------------------------------------------------
#define GSTR 36
#define GBUF (128 * GSTR)

__global__ __launch_bounds__(256) void gemm_tf32_kernel(
    const float* __restrict__ A_in,
    const float* __restrict__ W,
    const float* __restrict__ bi1,
    const float* __restrict__ bi2,
    int dst_sel, int M)
{
    const float* A = A_in ? A_in : g_h1;

    extern __shared__ unsigned gsm[];
    unsigned* As = gsm;
    unsigned* Bs = gsm + 2 * GBUF;

    const int tid = threadIdx.x;
    const int lane = tid & 31;
    const int warp = tid >> 5;
    const int g = lane >> 2;
    const int tig = lane & 3;
    const int wm = warp & 1;
    const int wn = warp >> 1;
    const int m0 = blockIdx.y * 128;
    const int n0 = blockIdx.x * 128;

    float acc[4][4][4];
#pragma unroll
    for (int i = 0; i < 4; i++)
#pragma unroll
        for (int j = 0; j < 4; j++)
#pragma unroll
            for (int e = 0; e < 4; e++) acc[i][j][e] = 0.0f;

    int lrow[4], lc[4];
#pragma unroll
    for (int p = 0; p < 4; p++) {
        int id = tid + p * 256;
        lrow[p] = id >> 3;
        lc[p] = (id & 7) * 4;
    }

    {
#pragma unroll
        for (int p = 0; p < 4; p++) {
            int r = lrow[p], kc = lc[p];
            float4 va = make_float4(0.f, 0.f, 0.f, 0.f);
            if (m0 + r < M) va = *(const float4*)(A + (size_t)(m0 + r) * 512 + kc);
            *(uint4*)(As + r * GSTR + kc) = *(const uint4*)&va;
            float4 vb = *(const float4*)(W + (size_t)(n0 + r) * 512 + kc);
            *(uint4*)(Bs + r * GSTR + kc) = *(const uint4*)&vb;
        }
    }
    __syncthreads();

    float4 pa[4], pb[4];
    for (int it = 0; it < 16; it++) {
        int buf = it & 1;
        if (it < 15) {
            int k0 = (it + 1) * 32;
#pragma unroll
            for (int p = 0; p < 4; p++) {
                int r = lrow[p], kc = lc[p];
                pa[p] = make_float4(0.f, 0.f, 0.f, 0.f);
                if (m0 + r < M) pa[p] = *(const float4*)(A + (size_t)(m0 + r) * 512 + k0 + kc);
                pb[p] = *(const float4*)(W + (size_t)(n0 + r) * 512 + k0 + kc);
            }
        }
        const unsigned* Ab = As + buf * GBUF;
        const unsigned* Bb = Bs + buf * GBUF;
#pragma unroll
        for (int kk = 0; kk < 4; kk++) {
            int kb = kk * 8;
            unsigned af[4][4];
#pragma unroll
            for (int mf = 0; mf < 4; mf++) {
                int r = wm * 64 + mf * 16 + g;
                af[mf][0] = Ab[r * GSTR + kb + tig];
                af[mf][1] = Ab[(r + 8) * GSTR + kb + tig];
                af[mf][2] = Ab[r * GSTR + kb + tig + 4];
                af[mf][3] = Ab[(r + 8) * GSTR + kb + tig + 4];
            }
            unsigned bf[4][2];
#pragma unroll
            for (int nf = 0; nf < 4; nf++) {
                int n = wn * 32 + nf * 8 + g;
                bf[nf][0] = Bb[n * GSTR + kb + tig];
                bf[nf][1] = Bb[n * GSTR + kb + tig + 4];
            }
#pragma unroll
            for (int mf = 0; mf < 4; mf++)
#pragma unroll
                for (int nf = 0; nf < 4; nf++)
                    mma_tf32(acc[mf][nf], af[mf], bf[nf]);
        }
        if (it < 15) {
            unsigned* Ad = As + (buf ^ 1) * GBUF;
            unsigned* Bd = Bs + (buf ^ 1) * GBUF;
#pragma unroll
            for (int p = 0; p < 4; p++) {
                int r = lrow[p], kc = lc[p];
                *(uint4*)(Ad + r * GSTR + kc) = *(const uint4*)&pa[p];
                *(uint4*)(Bd + r * GSTR + kc) = *(const uint4*)&pb[p];
            }
        }
        __syncthreads();
    }

    if (dst_sel) {
        // stage fp16 tile in smem as [t_loc][n_loc][b], then linear stores
        __half* ep = (__half*)gsm;
#pragma unroll
        for (int nf = 0; nf < 4; nf++) {
            int nl = wn * 32 + nf * 8 + 2 * tig;
            int n = n0 + nl;
            float bb0 = bi1[n] + bi2[n];
            float bb1 = bi1[n + 1] + bi2[n + 1];
#pragma unroll
            for (int mf = 0; mf < 4; mf++) {
                int m = wm * 64 + mf * 16 + g;
                int tl = m >> 6, b = m & 63;
                ep[tl * 8192 + nl * 64 + b]       = __float2half_rn(acc[mf][nf][0] + bb0);
                ep[tl * 8192 + (nl + 1) * 64 + b] = __float2half_rn(acc[mf][nf][1] + bb1);
                int m2 = m + 8;
                int tl2 = m2 >> 6, b2 = m2 & 63;
                ep[tl2 * 8192 + nl * 64 + b2]       = __float2half_rn(acc[mf][nf][2] + bb0);
                ep[tl2 * 8192 + (nl + 1) * 64 + b2] = __float2half_rn(acc[mf][nf][3] + bb1);
            }
        }
        __syncthreads();
        size_t base = (size_t)(m0 >> 6) * (G4 * 64) + (size_t)n0 * 64;
#pragma unroll
        for (int i = 0; i < 8; i++) {
            int idx4 = tid + i * 256;
            int tl = idx4 >> 10;
            int within = idx4 & 1023;
            uint4 v = *(const uint4*)(ep + idx4 * 8);
            *(uint4*)(g_xW1h + base + (size_t)tl * (G4 * 64) + within * 8) = v;
        }
    } else {
#pragma unroll
        for (int nf = 0; nf < 4; nf++) {
            int n = n0 + wn * 32 + nf * 8 + 2 * tig;
            float bb0 = bi1[n] + bi2[n];
            float bb1 = bi1[n + 1] + bi2[n + 1];
#pragma unroll
            for (int mf = 0; mf < 4; mf++) {
                int r = m0 + wm * 64 + mf * 16 + g;
                if (r < M) {
                    __half2 v = __floats2half2_rn(acc[mf][nf][0] + bb0, acc[mf][nf][1] + bb1);
                    *(__half2*)(g_E0h + (size_t)r * G4 + n) = v;
                }
                if (r + 8 < M) {
                    __half2 v = __floats2half2_rn(acc[mf][nf][2] + bb0, acc[mf][nf][3] + bb1);
                    *(__half2*)(g_E0h + (size_t)(r + 8) * G4 + n) = v;
                }
            }
        }
    }
}

// ---------------------------------------------------------------------------
// Persistent LSTM scan: 64 CTAs x 256 threads (8 warps), fp16 h, m16n8k16.
// Block owns 8 units = 32 gate rows (row n: unit n>>2, gate n&3).
// Warp roles: wm = w&1 (batches wm*32+32), wn = (w>>1)&1 (rows wn*16+16),
//             ks = w>>2 (k half: [ks*256, ks*256+256)).
//   per warp: m32 x n16 x k256 = 32 LDS.128 + 64 HMMA; B frags in 64 regs.
// Full h (64 KB) staged block-cooperatively via cp.async each step
//   (chip broadcast = 64 x 64 KB = 4 MB/step, half of the 128-CTA version).
// 2-way k-split reduced via smem red into the cell phase (cell: warp = unit).
// Grid barrier: single-counter red.release + 64 pollers on one word (R6-proven).
// ---------------------------------------------------------------------------
__global__ __launch_bounds__(SCAN_THREADS) void lstm_scan_kernel(
    const int* __restrict__ src,        // nullptr for layer 1
    const float* __restrict__ Whh,
    const int* __restrict__ sen_len,    // nullptr for layer 0
    float* __restrict__ final_out)      // nullptr for layer 0
{
    extern __shared__ unsigned ssm[];
    unsigned* sh_h = ssm;                            // 16384 u32 = full 64KB fp16 h
    float* red = (float*)(ssm + 16384);              // [2][64][RSTR]
    float* hex = (float*)(ssm + 16384 + 2 * 64 * RSTR);   // [8][64]

    const int tid = threadIdx.x;
    const int lane = tid & 31;
    const int warp = tid >> 5;         // 0..7
    const int g = lane >> 2;
    const int tig = lane & 3;
    const int wm = warp & 1;
    const int wn = (warp >> 1) & 1;
    const int ks = warp >> 2;
    const int u0 = blockIdx.x * 8;
    const int b0 = lane, b1 = lane + 32;
    const int ju = warp;               // unit handled in cell phase
    const unsigned nblk = gridDim.x;

    unsigned sh_base;
    asm("{ .reg .u64 t; cvta.to.shared.u64 t, %1; cvt.u32.u64 %0, t; }"
        : "=r"(sh_base) : "l"((void*)ssm));

    // ---- B (Whh) fp16 fragments in registers, once per scan ----
    // breg[kk][nt]: k-chunk kk within this warp's k-half, rows wn*16+nt*8+g.
    unsigned breg[16][2][2];
#pragma unroll
    for (int kk = 0; kk < 16; kk++) {
#pragma unroll
        for (int nt = 0; nt < 2; nt++) {
            int n = wn * 16 + nt * 8 + g;
            int row = (n & 3) * 512 + u0 + (n >> 2);
            const float* wr = Whh + (size_t)row * 512 + ks * 256 + kk * 16;
            __half2 h0 = __floats2half2_rn(wr[2 * tig], wr[2 * tig + 1]);
            __half2 h1 = __floats2half2_rn(wr[2 * tig + 8], wr[2 * tig + 9]);
            breg[kk][nt][0] = *(unsigned*)&h0;
            breg[kk][nt][1] = *(unsigned*)&h1;
        }
    }

    float c_0 = 0.0f, c_1 = 0.0f;
    int sl0 = -1, sl1 = -1;
    if (sen_len) { sl0 = sen_len[b0]; sl1 = sen_len[b1]; }

    const int u_cell = u0 + ju;
    const int hi0 = hidx16(b0, u_cell);
    const int hi1 = hidx16(b1, u_cell);

    for (int t = 0; t < T_LEN; t++) {
        // ---- stage full h (64 KB) block-cooperatively via cp.async ----
        {
            const uint4* hs = (const uint4*)(g_hbuf16[t & 1]) + tid;
            unsigned sd = sh_base + (unsigned)(tid * 16);
#pragma unroll 8
            for (int i = 0; i < 16; i++)
                cp16(sd + i * 4096, hs + i * 256);
            asm volatile("cp.async.commit_group;");
        }

        // ---- prefetch cell inputs (fp16, independent of h) ----
        float p0[4], p1[4];
        if (src) {
            int r0 = src[t * NBATCH + b0];
            int r1 = src[t * NBATCH + b1];
            const __half* e0 = g_E0h + (size_t)r0 * G4 + u_cell;
            const __half* e1 = g_E0h + (size_t)r1 * G4 + u_cell;
#pragma unroll
            for (int gt = 0; gt < 4; gt++) {
                p0[gt] = __half2float(e0[gt * 512]);
                p1[gt] = __half2float(e1[gt * 512]);
            }
        } else {
            const __half* xb = g_xW1h + (size_t)t * (G4 * 64) + (size_t)u_cell * 64;
#pragma unroll
            for (int gt = 0; gt < 4; gt++) {
                p0[gt] = __half2float(xb[gt * 32768 + b0]);
                p1[gt] = __half2float(xb[gt * 32768 + b1]);
            }
        }

        asm volatile("cp.async.wait_group 0;" ::: "memory");
        __syncthreads();   // staging is cross-thread: block-wide completion

        // ---- mma: m32 x n16 x k256 per warp (f16, fp32 acc) ----
        float acc[2][2][4];
#pragma unroll
        for (int mt2 = 0; mt2 < 2; mt2++)
#pragma unroll
            for (int nt = 0; nt < 2; nt++)
#pragma unroll
                for (int e = 0; e < 4; e++) acc[mt2][nt][e] = 0.0f;

#pragma unroll
        for (int kk = 0; kk < 16; kk++) {
            int kkg = ks * 16 + kk;
#pragma unroll
            for (int mt2 = 0; mt2 < 2; mt2++) {
                int mt = wm * 2 + mt2;
                uint4 a = *(const uint4*)(sh_h + ((kkg * 4 + mt) * 32 + lane) * 4);
                mma_f16(acc[mt2][0], (const unsigned*)&a, breg[kk][0]);
                mma_f16(acc[mt2][1], (const unsigned*)&a, breg[kk][1]);
            }
        }

        // ---- store k-split partials: red[ks][batch][n] ----
#pragma unroll
        for (int mt2 = 0; mt2 < 2; mt2++)
#pragma unroll
            for (int nt = 0; nt < 2; nt++) {
                int bb = wm * 32 + mt2 * 16 + g;
                float* rp = &red[(ks * 64 + bb) * RSTR + wn * 16 + nt * 8 + 2 * tig];
                *(float2*)rp = make_float2(acc[mt2][nt][0], acc[mt2][nt][1]);
                *(float2*)(rp + 8 * RSTR) = make_float2(acc[mt2][nt][2], acc[mt2][nt][3]);
            }
        __syncthreads();

        // ---- cell phase: thread = (unit ju, batches b0/b1) ----
        float z0[4], z1[4];
        {
            float4 v00 = *(const float4*)&red[(b0) * RSTR + ju * 4];
            float4 v01 = *(const float4*)&red[(64 + b0) * RSTR + ju * 4];
            float4 v10 = *(const float4*)&red[(b1) * RSTR + ju * 4];
            float4 v11 = *(const float4*)&red[(64 + b1) * RSTR + ju * 4];
            z0[0] = p0[0] + v00.x + v01.x; z0[1] = p0[1] + v00.y + v01.y;
            z0[2] = p0[2] + v00.z + v01.z; z0[3] = p0[3] + v00.w + v01.w;
            z1[0] = p1[0] + v10.x + v11.x; z1[1] = p1[1] + v10.y + v11.y;
            z1[2] = p1[2] + v10.z + v11.z; z1[3] = p1[3] + v10.w + v11.w;
        }

        float i0 = sig_(z0[0]), f0 = sig_(z0[1]), gg0 = tanh_ap(z0[2]), o0 = sig_(z0[3]);
        c_0 = f0 * c_0 + i0 * gg0;
        float h0n = o0 * tanh_ap(c_0);

        float i1 = sig_(z1[0]), f1 = sig_(z1[1]), gg1 = tanh_ap(z1[2]), o1 = sig_(z1[3]);
        c_1 = f1 * c_1 + i1 * gg1;
        float h1n = o1 * tanh_ap(c_1);

        __half* hd = g_hbuf16[(t + 1) & 1];
        hd[hi0] = __float2half_rn(h0n);
        hd[hi1] = __float2half_rn(h1n);

        if (src) {
            hex[ju * 64 + b0] = h0n;
            hex[ju * 64 + b1] = h1n;
        } else {
            if (t == sl0 - 1) final_out[b0 * HID + u_cell] = h0n;
            if (t == sl1 - 1) final_out[b1 * HID + u_cell] = h1n;
        }

        // ---- grid barrier (single counter, release/acquire; 64 blocks) ----
        __syncthreads();   // orders h/hex writes before release
        if (src && tid < 64) {
            int b = tid;
            float4 v0 = make_float4(hex[b], hex[64 + b], hex[128 + b], hex[192 + b]);
            float4 v1 = make_float4(hex[256 + b], hex[320 + b], hex[384 + b], hex[448 + b]);
            float* gp = g_h1 + (size_t)(t * NBATCH + b) * HID + u0;
            *(float4*)gp = v0;
            *(float4*)(gp + 4) = v1;
        }
        if (tid == 0) {
            asm volatile("red.release.gpu.global.add.u32 [%0], 1;"
                         :: "l"(&g_ctr) : "memory");
            unsigned tgt = nblk * (unsigned)(t + 1);
            while (ld_acq(&g_ctr) < tgt) { }
        }
        __syncthreads();
    }
}

// ---------------------------------------------------------------------------
extern "C" void kernel_launch(void* const* d_in, const int* in_sizes, int n_in,
                              void* d_out, int out_size)
{
    const int*   src       = (const int*)  d_in[0];
    const int*   sen_len   = (const int*)  d_in[1];
    const float* emb_table = (const float*)d_in[2];
    const float* Wih0      = (const float*)d_in[3];
    const float* Whh0      = (const float*)d_in[4];
    const float* bih0      = (const float*)d_in[5];
    const float* bhh0      = (const float*)d_in[6];
    const float* Wih1      = (const float*)d_in[7];
    const float* Whh1      = (const float*)d_in[8];
    const float* bih1      = (const float*)d_in[9];
    const float* bhh1      = (const float*)d_in[10];
    float* out = (float*)d_out;

    const size_t gemm_smem = (size_t)4 * GBUF * sizeof(unsigned);     // 73728 B
    const size_t scan_smem =
        (size_t)(16384 + 2 * 64 * RSTR + 8 * 64) * sizeof(unsigned);  // 86016 B
    cudaFuncSetAttribute(gemm_tf32_kernel,
                         cudaFuncAttributeMaxDynamicSharedMemorySize, (int)gemm_smem);
    cudaFuncSetAttribute(lstm_scan_kernel,
                         cudaFuncAttributeMaxDynamicSharedMemorySize, (int)scan_smem);

    // Phase 0: E0 = emb_table @ Wih0^T + b0   (10000 x 2048, fp16 out)
    {
        dim3 grid(G4 / 128, (NVOCAB + 127) / 128);
        gemm_tf32_kernel<<<grid, 256, gemm_smem>>>(emb_table, Wih0, bih0, bhh0, 0, NVOCAB);
    }

    // Phase 1: layer-0 scan
    zero_init_kernel<<<64, 512>>>();
    lstm_scan_kernel<<<SCAN_BLOCKS, SCAN_THREADS, scan_smem>>>(
        src, Whh0, nullptr, nullptr);

    // Phase 2: xW1 = h1 @ Wih1^T + b1  -> fp16 [t][r][b]
    {
        dim3 grid(G4 / 128, (T_LEN * NBATCH) / 128);
        gemm_tf32_kernel<<<grid, 256, gemm_smem>>>(nullptr, Wih1, bih1, bhh1, 1,
                                                   T_LEN * NBATCH);
    }

    // Phase 3: layer-1 scan (+ final gather at sen_len-1)
    zero_init_kernel<<<64, 512>>>();
    lstm_scan_kernel<<<SCAN_BLOCKS, SCAN_THREADS, scan_smem>>>(
        nullptr, Whh1, sen_len, out);
}

// round 9
// speedup vs baseline: 3.0824x; 1.9672x over previous
#include <cuda_runtime.h>
#include <cuda_fp16.h>
#include <math.h>
#include <stdint.h>

// Problem constants
#define T_LEN 512
#define NBATCH 64
#define HID 512
#define G4 2048          // 4*HID
#define NVOCAB 10000

#define SCAN_BLOCKS 128
#define SCAN_THREADS 128
#define RPAD 20          // red buffer row pad (floats)

// -------- device scratch --------
__device__ __align__(16) __half g_E0h[(size_t)NVOCAB * G4];   // emb @ Wih0^T + b0 (fp16)
__device__ __align__(16) __half g_h0buf[2][NBATCH * HID];     // layer0 h ping-pong, frag layout
__device__ __align__(16) __half g_h1buf[2][NBATCH * HID];     // layer1 h ping-pong, frag layout
__device__ unsigned g_ctr;                                     // barrier counter (monotonic)

// ---------------- helpers ----------------
__device__ __forceinline__ void mma_tf32(float* c, const unsigned* a, const unsigned* b) {
    asm("mma.sync.aligned.m16n8k8.row.col.f32.tf32.tf32.f32 "
        "{%0,%1,%2,%3}, {%4,%5,%6,%7}, {%8,%9}, {%0,%1,%2,%3};"
        : "+f"(c[0]), "+f"(c[1]), "+f"(c[2]), "+f"(c[3])
        : "r"(a[0]), "r"(a[1]), "r"(a[2]), "r"(a[3]), "r"(b[0]), "r"(b[1]));
}
__device__ __forceinline__ void mma_f16(float* c, const unsigned* a, const unsigned* b) {
    asm("mma.sync.aligned.m16n8k16.row.col.f32.f16.f16.f32 "
        "{%0,%1,%2,%3}, {%4,%5,%6,%7}, {%8,%9}, {%0,%1,%2,%3};"
        : "+f"(c[0]), "+f"(c[1]), "+f"(c[2]), "+f"(c[3])
        : "r"(a[0]), "r"(a[1]), "r"(a[2]), "r"(a[3]), "r"(b[0]), "r"(b[1]));
}
__device__ __forceinline__ unsigned ld_acq(const unsigned* p) {
    unsigned v; asm volatile("ld.acquire.gpu.global.u32 %0, [%1];" : "=r"(v) : "l"(p)); return v;
}
__device__ __forceinline__ void cp16(unsigned sdst, const void* gsrc) {
    asm volatile("cp.async.cg.shared.global [%0], [%1], 16;" :: "r"(sdst), "l"(gsrc));
}
__device__ __forceinline__ float tanh_ap(float x) {
    float y; asm("tanh.approx.f32 %0, %1;" : "=f"(y) : "f"(x)); return y;
}
__device__ __forceinline__ float sig_(float x) {
    return __fdividef(1.0f, 1.0f + __expf(-x));
}
// fp16 half-index for h value (batch b, unit k) in m16n8k16 A-fragment layout.
__device__ __forceinline__ int hidx16(int b, int k) {
    int kk = k >> 4, mt = b >> 4, r = b & 15, kl = k & 15;
    int lane = (r & 7) * 4 + ((kl & 7) >> 1);
    int w = ((kl >> 3) << 1) | (r >> 3);
    return (((kk * 4 + mt) * 32 + lane) * 4 + w) * 2 + (k & 1);
}

// ---------------------------------------------------------------------------
__global__ void zero_init_kernel() {
    int i = blockIdx.x * blockDim.x + threadIdx.x;
    if (i < 2 * (NBATCH * HID) / 2) {          // both parities of h0 (as u32)
        ((unsigned*)g_h0buf)[i] = 0u;
        ((unsigned*)g_h1buf)[i] = 0u;
    }
    if (i == 0) g_ctr = 0u;
}

// ---------------------------------------------------------------------------
// tf32 tensor-core GEMM: g_E0h[M][2048] = A[M][512] @ W[2048][512]^T + (b1+b2)
// fp16 output. Raw fp32 bits fed to HMMA.TF32 (HW truncates mantissa).
// ---------------------------------------------------------------------------
#define GSTR 36
#define GBUF (128 * GSTR)

__global__ __launch_bounds__(256) void gemm_e0_kernel(
    const float* __restrict__ A,
    const float* __restrict__ W,
    const float* __restrict__ bi1,
    const float* __restrict__ bi2,
    int M)
{
    extern __shared__ unsigned gsm[];
    unsigned* As = gsm;
    unsigned* Bs = gsm + 2 * GBUF;

    const int tid = threadIdx.x;
    const int lane = tid & 31;
    const int warp = tid >> 5;
    const int g = lane >> 2;
    const int tig = lane & 3;
    const int wm = warp & 1;
    const int wn = warp >> 1;
    const int m0 = blockIdx.y * 128;
    const int n0 = blockIdx.x * 128;

    float acc[4][4][4];
#pragma unroll
    for (int i = 0; i < 4; i++)
#pragma unroll
        for (int j = 0; j < 4; j++)
#pragma unroll
            for (int e = 0; e < 4; e++) acc[i][j][e] = 0.0f;

    int lrow[4], lc[4];
#pragma unroll
    for (int p = 0; p < 4; p++) {
        int id = tid + p * 256;
        lrow[p] = id >> 3;
        lc[p] = (id & 7) * 4;
    }

    {
#pragma unroll
        for (int p = 0; p < 4; p++) {
            int r = lrow[p], kc = lc[p];
            float4 va = make_float4(0.f, 0.f, 0.f, 0.f);
            if (m0 + r < M) va = *(const float4*)(A + (size_t)(m0 + r) * 512 + kc);
            *(uint4*)(As + r * GSTR + kc) = *(const uint4*)&va;
            float4 vb = *(const float4*)(W + (size_t)(n0 + r) * 512 + kc);
            *(uint4*)(Bs + r * GSTR + kc) = *(const uint4*)&vb;
        }
    }
    __syncthreads();

    float4 pa[4], pb[4];
    for (int it = 0; it < 16; it++) {
        int buf = it & 1;
        if (it < 15) {
            int k0 = (it + 1) * 32;
#pragma unroll
            for (int p = 0; p < 4; p++) {
                int r = lrow[p], kc = lc[p];
                pa[p] = make_float4(0.f, 0.f, 0.f, 0.f);
                if (m0 + r < M) pa[p] = *(const float4*)(A + (size_t)(m0 + r) * 512 + k0 + kc);
                pb[p] = *(const float4*)(W + (size_t)(n0 + r) * 512 + k0 + kc);
            }
        }
        const unsigned* Ab = As + buf * GBUF;
        const unsigned* Bb = Bs + buf * GBUF;
#pragma unroll
        for (int kk = 0; kk < 4; kk++) {
            int kb = kk * 8;
            unsigned af[4][4];
#pragma unroll
            for (int mf = 0; mf < 4; mf++) {
                int r = wm * 64 + mf * 16 + g;
                af[mf][0] = Ab[r * GSTR + kb + tig];
                af[mf][1] = Ab[(r + 8) * GSTR + kb + tig];
                af[mf][2] = Ab[r * GSTR + kb + tig + 4];
                af[mf][3] = Ab[(r + 8) * GSTR + kb + tig + 4];
            }
            unsigned bf[4][2];
#pragma unroll
            for (int nf = 0; nf < 4; nf++) {
                int n = wn * 32 + nf * 8 + g;
                bf[nf][0] = Bb[n * GSTR + kb + tig];
                bf[nf][1] = Bb[n * GSTR + kb + tig + 4];
            }
#pragma unroll
            for (int mf = 0; mf < 4; mf++)
#pragma unroll
                for (int nf = 0; nf < 4; nf++)
                    mma_tf32(acc[mf][nf], af[mf], bf[nf]);
        }
        if (it < 15) {
            unsigned* Ad = As + (buf ^ 1) * GBUF;
            unsigned* Bd = Bs + (buf ^ 1) * GBUF;
#pragma unroll
            for (int p = 0; p < 4; p++) {
                int r = lrow[p], kc = lc[p];
                *(uint4*)(Ad + r * GSTR + kc) = *(const uint4*)&pa[p];
                *(uint4*)(Bd + r * GSTR + kc) = *(const uint4*)&pb[p];
            }
        }
        __syncthreads();
    }

#pragma unroll
    for (int nf = 0; nf < 4; nf++) {
        int n = n0 + wn * 32 + nf * 8 + 2 * tig;
        float bb0 = bi1[n] + bi2[n];
        float bb1 = bi1[n + 1] + bi2[n + 1];
#pragma unroll
        for (int mf = 0; mf < 4; mf++) {
            int r = m0 + wm * 64 + mf * 16 + g;
            if (r < M) {
                __half2 v = __floats2half2_rn(acc[mf][nf][0] + bb0, acc[mf][nf][1] + bb1);
                *(__half2*)(g_E0h + (size_t)r * G4 + n) = v;
            }
            if (r + 8 < M) {
                __half2 v = __floats2half2_rn(acc[mf][nf][2] + bb0, acc[mf][nf][3] + bb1);
                *(__half2*)(g_E0h + (size_t)(r + 8) * G4 + n) = v;
            }
        }
    }
}

// ---------------------------------------------------------------------------
// Fused two-layer pipelined LSTM scan. 128 CTAs x 128 threads (R6-proven
// shape). 513 iterations; at iter t: layer0 computes h_l0[t] (t<512) and
// layer1 computes h_l1[t-1] (t>=1) in the same barrier interval.
//   - layer1's input projection is a third in-scan mma (Wih1) that REUSES
//     the staged A-fragments of h_l0[t-1] (also consumed by nothing else
//     in layer0's GEMM loop beyond the shared load).
//   - block owns 4 units per layer (rows n: unit n>>2, gate n&3).
//   - warp w = k-slice [128w,128w+128): per step 64 LDS.128 + 192 HMMA.
//   - buffers: h0buf write t&1 / read (t+1)&1; h1buf write (t-1)&1 / read t&1.
//   - grid barrier: single-counter red.release + one-word acquire poll.
// ---------------------------------------------------------------------------
__global__ __launch_bounds__(SCAN_THREADS) void lstm_fused_kernel(
    const int* __restrict__ src,
    const float* __restrict__ Whh0,
    const float* __restrict__ Wih1,
    const float* __restrict__ Whh1,
    const float* __restrict__ bih1,
    const float* __restrict__ bhh1,
    const int* __restrict__ sen_len,
    float* __restrict__ final_out)
{
    extern __shared__ unsigned ssm[];
    unsigned* sh_h0 = ssm;                         // 16384 u32 (64 KB fp16)
    unsigned* sh_h1 = ssm + 16384;                 // 16384 u32
    float* red0 = (float*)(ssm + 32768);           // [4][64][RPAD]
    float* red1 = red0 + 4 * 64 * RPAD;            // [4][64][RPAD]

    const int tid = threadIdx.x;
    const int lane = tid & 31;
    const int warp = tid >> 5;       // 0..3 = k-slice
    const int g = lane >> 2;
    const int tig = lane & 3;
    const int u0 = blockIdx.x * 4;
    const int b0 = lane, b1 = lane + 32;
    const int ug = warp;             // unit handled in cell phase
    const unsigned nblk = gridDim.x;

    unsigned sh_base;
    asm("{ .reg .u64 t; cvta.to.shared.u64 t, %1; cvt.u32.u64 %0, t; }"
        : "=r"(sh_base) : "l"((void*)ssm));

    // ---- B fragments in registers (once): Whh0, Wih1, Whh1 ----
    unsigned breg0[8][2][2], bregI[8][2][2], bregU[8][2][2];
#pragma unroll
    for (int kkl = 0; kkl < 8; kkl++) {
#pragma unroll
        for (int nt = 0; nt < 2; nt++) {
            int n = nt * 8 + g;
            size_t row = (size_t)((n & 3) * 512 + u0 + (n >> 2)) * 512
                       + warp * 128 + kkl * 16;
            {
                const float* wr = Whh0 + row;
                __half2 h0 = __floats2half2_rn(wr[2 * tig], wr[2 * tig + 1]);
                __half2 h1 = __floats2half2_rn(wr[2 * tig + 8], wr[2 * tig + 9]);
                breg0[kkl][nt][0] = *(unsigned*)&h0;
                breg0[kkl][nt][1] = *(unsigned*)&h1;
            }
            {
                const float* wr = Wih1 + row;
                __half2 h0 = __floats2half2_rn(wr[2 * tig], wr[2 * tig + 1]);
                __half2 h1 = __floats2half2_rn(wr[2 * tig + 8], wr[2 * tig + 9]);
                bregI[kkl][nt][0] = *(unsigned*)&h0;
                bregI[kkl][nt][1] = *(unsigned*)&h1;
            }
            {
                const float* wr = Whh1 + row;
                __half2 h0 = __floats2half2_rn(wr[2 * tig], wr[2 * tig + 1]);
                __half2 h1 = __floats2half2_rn(wr[2 * tig + 8], wr[2 * tig + 9]);
                bregU[kkl][nt][0] = *(unsigned*)&h0;
                bregU[kkl][nt][1] = *(unsigned*)&h1;
            }
        }
    }

    const int u_cell = u0 + ug;
    // layer1 cell bias (bih1+bhh1), per gate
    float bsum[4];
#pragma unroll
    for (int gt = 0; gt < 4; gt++)
        bsum[gt] = bih1[gt * 512 + u_cell] + bhh1[gt * 512 + u_cell];

    float c00 = 0.f, c01 = 0.f;   // layer0 cell state, batches b0/b1
    float c10 = 0.f, c11 = 0.f;   // layer1
    const int sl0 = sen_len[b0], sl1 = sen_len[b1];

    const int hi0 = hidx16(b0, u_cell);
    const int hi1 = hidx16(b1, u_cell);

    for (int t = 0; t <= T_LEN; t++) {
        const bool do_l0 = (t < T_LEN);
        const bool do_l1 = (t >= 1);

        // ---- stage h_l0[t-1] and h_l1[t-2] (16 KB each per warp) ----
        {
            const uint4* hs0 = (const uint4*)(g_h0buf[(t + 1) & 1]) + warp * 1024 + lane;
            unsigned sd0 = sh_base + (unsigned)(warp * 16384 + lane * 16);
            const uint4* hs1 = (const uint4*)(g_h1buf[t & 1]) + warp * 1024 + lane;
            unsigned sd1 = sh_base + (unsigned)(65536 + warp * 16384 + lane * 16);
#pragma unroll 8
            for (int i = 0; i < 32; i++) {
                cp16(sd0 + i * 512, hs0 + i * 32);
                cp16(sd1 + i * 512, hs1 + i * 32);
            }
            asm volatile("cp.async.commit_group;");
        }

        // ---- prefetch layer0 cell inputs (E0 gather; overlaps cp.async) ----
        float p0[4], p1[4];
        {
            int tt = do_l0 ? t : T_LEN - 1;
            int r0 = src[tt * NBATCH + b0];
            int r1 = src[tt * NBATCH + b1];
            const __half* e0 = g_E0h + (size_t)r0 * G4 + u_cell;
            const __half* e1 = g_E0h + (size_t)r1 * G4 + u_cell;
#pragma unroll
            for (int gt = 0; gt < 4; gt++) {
                p0[gt] = __half2float(e0[gt * 512]);
                p1[gt] = __half2float(e1[gt * 512]);
            }
        }

        asm volatile("cp.async.wait_group 0;" ::: "memory");
        __syncwarp();

        // ---- layer0 rec mma + layer1 input-proj mma (shared A frags) ----
        {
            float acc0[4][2][4], acc1[4][2][4];
#pragma unroll
            for (int mt = 0; mt < 4; mt++)
#pragma unroll
                for (int nt = 0; nt < 2; nt++)
#pragma unroll
                    for (int e = 0; e < 4; e++) { acc0[mt][nt][e] = 0.f; acc1[mt][nt][e] = 0.f; }

#pragma unroll
            for (int kkl = 0; kkl < 8; kkl++) {
                int kkg = warp * 8 + kkl;
#pragma unroll
                for (int mt = 0; mt < 4; mt++) {
                    uint4 a = *(const uint4*)(sh_h0 + ((kkg * 4 + mt) * 32 + lane) * 4);
                    mma_f16(acc0[mt][0], (const unsigned*)&a, breg0[kkl][0]);
                    mma_f16(acc0[mt][1], (const unsigned*)&a, breg0[kkl][1]);
                    mma_f16(acc1[mt][0], (const unsigned*)&a, bregI[kkl][0]);
                    mma_f16(acc1[mt][1], (const unsigned*)&a, bregI[kkl][1]);
                }
            }
            // layer1 recurrent mma on h_l1[t-2]
#pragma unroll
            for (int kkl = 0; kkl < 8; kkl++) {
                int kkg = warp * 8 + kkl;
#pragma unroll
                for (int mt = 0; mt < 4; mt++) {
                    uint4 a = *(const uint4*)(sh_h1 + ((kkg * 4 + mt) * 32 + lane) * 4);
                    mma_f16(acc1[mt][0], (const unsigned*)&a, bregU[kkl][0]);
                    mma_f16(acc1[mt][1], (const unsigned*)&a, bregU[kkl][1]);
                }
            }

            // ---- store k-partials ----
#pragma unroll
            for (int mt = 0; mt < 4; mt++)
#pragma unroll
                for (int nt = 0; nt < 2; nt++) {
                    int bb = mt * 16 + g;
                    float* rp0 = &red0[(warp * 64 + bb) * RPAD + nt * 8 + 2 * tig];
                    *(float2*)rp0 = make_float2(acc0[mt][nt][0], acc0[mt][nt][1]);
                    *(float2*)(rp0 + 8 * RPAD) = make_float2(acc0[mt][nt][2], acc0[mt][nt][3]);
                    float* rp1 = &red1[(warp * 64 + bb) * RPAD + nt * 8 + 2 * tig];
                    *(float2*)rp1 = make_float2(acc1[mt][nt][0], acc1[mt][nt][1]);
                    *(float2*)(rp1 + 8 * RPAD) = make_float2(acc1[mt][nt][2], acc1[mt][nt][3]);
                }
        }
        __syncthreads();

        // ---- layer0 cell ----
        if (do_l0) {
            float z0[4], z1[4];
#pragma unroll
            for (int gt = 0; gt < 4; gt++) { z0[gt] = p0[gt]; z1[gt] = p1[gt]; }
#pragma unroll
            for (int w = 0; w < 4; w++) {
                float4 v0 = *(const float4*)&red0[(w * 64 + b0) * RPAD + ug * 4];
                float4 v1 = *(const float4*)&red0[(w * 64 + b1) * RPAD + ug * 4];
                z0[0] += v0.x; z0[1] += v0.y; z0[2] += v0.z; z0[3] += v0.w;
                z1[0] += v1.x; z1[1] += v1.y; z1[2] += v1.z; z1[3] += v1.w;
            }
            float i0 = sig_(z0[0]), f0 = sig_(z0[1]), gg0 = tanh_ap(z0[2]), o0 = sig_(z0[3]);
            c00 = f0 * c00 + i0 * gg0;
            float h0n = o0 * tanh_ap(c00);
            float i1 = sig_(z1[0]), f1 = sig_(z1[1]), gg1 = tanh_ap(z1[2]), o1 = sig_(z1[3]);
            c01 = f1 * c01 + i1 * gg1;
            float h1n = o1 * tanh_ap(c01);

            __half* hd = g_h0buf[t & 1];
            hd[hi0] = __float2half_rn(h0n);
            hd[hi1] = __float2half_rn(h1n);
        }

        // ---- layer1 cell (computes h_l1[t-1]) ----
        if (do_l1) {
            float z0[4], z1[4];
#pragma unroll
            for (int gt = 0; gt < 4; gt++) { z0[gt] = bsum[gt]; z1[gt] = bsum[gt]; }
#pragma unroll
            for (int w = 0; w < 4; w++) {
                float4 v0 = *(const float4*)&red1[(w * 64 + b0) * RPAD + ug * 4];
                float4 v1 = *(const float4*)&red1[(w * 64 + b1) * RPAD + ug * 4];
                z0[0] += v0.x; z0[1] += v0.y; z0[2] += v0.z; z0[3] += v0.w;
                z1[0] += v1.x; z1[1] += v1.y; z1[2] += v1.z; z1[3] += v1.w;
            }
            float i0 = sig_(z0[0]), f0 = sig_(z0[1]), gg0 = tanh_ap(z0[2]), o0 = sig_(z0[3]);
            c10 = f0 * c10 + i0 * gg0;
            float h0n = o0 * tanh_ap(c10);
            float i1 = sig_(z1[0]), f1 = sig_(z1[1]), gg1 = tanh_ap(z1[2]), o1 = sig_(z1[3]);
            c11 = f1 * c11 + i1 * gg1;
            float h1n = o1 * tanh_ap(c11);

            __half* hd = g_h1buf[(t - 1) & 1];
            hd[hi0] = __float2half_rn(h0n);
            hd[hi1] = __float2half_rn(h1n);

            // outputs[sen_len-1] gather: h_l1[t-1] with t-1 == sl-1  <=>  t == sl
            if (t == sl0) final_out[b0 * HID + u_cell] = h0n;
            if (t == sl1) final_out[b1 * HID + u_cell] = h1n;
        }

        // ---- grid barrier (single counter, release/acquire) ----
        __syncthreads();   // all h stores issued block-wide
        if (tid == 0) {
            asm volatile("red.release.gpu.global.add.u32 [%0], 1;"
                         :: "l"(&g_ctr) : "memory");
            unsigned tgt = nblk * (unsigned)(t + 1);
            while (ld_acq(&g_ctr) < tgt) { }
        }
        __syncthreads();
    }
}

// ---------------------------------------------------------------------------
extern "C" void kernel_launch(void* const* d_in, const int* in_sizes, int n_in,
                              void* d_out, int out_size)
{
    const int*   src       = (const int*)  d_in[0];
    const int*   sen_len   = (const int*)  d_in[1];
    const float* emb_table = (const float*)d_in[2];
    const float* Wih0      = (const float*)d_in[3];
    const float* Whh0      = (const float*)d_in[4];
    const float* bih0      = (const float*)d_in[5];
    const float* bhh0      = (const float*)d_in[6];
    const float* Wih1      = (const float*)d_in[7];
    const float* Whh1      = (const float*)d_in[8];
    const float* bih1      = (const float*)d_in[9];
    const float* bhh1      = (const float*)d_in[10];
    float* out = (float*)d_out;

    const size_t gemm_smem = (size_t)4 * GBUF * sizeof(unsigned);        // 73728 B
    const size_t scan_smem =
        (size_t)(32768 + 2 * 4 * 64 * RPAD) * sizeof(unsigned);          // 172032 B
    cudaFuncSetAttribute(gemm_e0_kernel,
                         cudaFuncAttributeMaxDynamicSharedMemorySize, (int)gemm_smem);
    cudaFuncSetAttribute(lstm_fused_kernel,
                         cudaFuncAttributeMaxDynamicSharedMemorySize, (int)scan_smem);

    // Phase 0: E0 = emb_table @ Wih0^T + (bih0+bhh0)   (10000 x 2048, fp16)
    {
        dim3 grid(G4 / 128, (NVOCAB + 127) / 128);
        gemm_e0_kernel<<<grid, 256, gemm_smem>>>(emb_table, Wih0, bih0, bhh0, NVOCAB);
    }

    // Phase 1: fused two-layer pipelined scan (513 iterations)
    zero_init_kernel<<<128, 512>>>();
    lstm_fused_kernel<<<SCAN_BLOCKS, SCAN_THREADS, scan_smem>>>(
        src, Whh0, Wih1, Whh1, bih1, bhh1, sen_len, out);
}

// round 10
// speedup vs baseline: 3.4541x; 1.1206x over previous
#include <cuda_runtime.h>
#include <cuda_fp16.h>
#include <math.h>
#include <stdint.h>

// Problem constants
#define T_LEN 512
#define NBATCH 64
#define HID 512
#define G4 2048          // 4*HID
#define NVOCAB 10000

#define SCAN_BLOCKS 128
#define SCAN_THREADS 256
#define NPAD 36          // red buffer row stride (floats)

// -------- device scratch --------
__device__ __align__(16) __half g_E0h[(size_t)NVOCAB * G4];   // emb @ Wih0^T + b0 (fp16)
__device__ __align__(16) __half g_h0buf[2][NBATCH * HID];     // layer0 h ping-pong, frag layout
__device__ __align__(16) __half g_h1buf[2][NBATCH * HID];     // layer1 h ping-pong, frag layout
__device__ unsigned g_ctr;                                     // barrier counter (monotonic)
__device__ int g_maxsl;                                        // max(sen_len)

// ---------------- helpers ----------------
__device__ __forceinline__ void mma_tf32(float* c, const unsigned* a, const unsigned* b) {
    asm("mma.sync.aligned.m16n8k8.row.col.f32.tf32.tf32.f32 "
        "{%0,%1,%2,%3}, {%4,%5,%6,%7}, {%8,%9}, {%0,%1,%2,%3};"
        : "+f"(c[0]), "+f"(c[1]), "+f"(c[2]), "+f"(c[3])
        : "r"(a[0]), "r"(a[1]), "r"(a[2]), "r"(a[3]), "r"(b[0]), "r"(b[1]));
}
__device__ __forceinline__ void mma_f16(float* c, const unsigned* a, const unsigned* b) {
    asm("mma.sync.aligned.m16n8k16.row.col.f32.f16.f16.f32 "
        "{%0,%1,%2,%3}, {%4,%5,%6,%7}, {%8,%9}, {%0,%1,%2,%3};"
        : "+f"(c[0]), "+f"(c[1]), "+f"(c[2]), "+f"(c[3])
        : "r"(a[0]), "r"(a[1]), "r"(a[2]), "r"(a[3]), "r"(b[0]), "r"(b[1]));
}
__device__ __forceinline__ unsigned ld_acq(const unsigned* p) {
    unsigned v; asm volatile("ld.acquire.gpu.global.u32 %0, [%1];" : "=r"(v) : "l"(p)); return v;
}
__device__ __forceinline__ void cp16(unsigned sdst, const void* gsrc) {
    asm volatile("cp.async.cg.shared.global [%0], [%1], 16;" :: "r"(sdst), "l"(gsrc));
}
__device__ __forceinline__ float tanh_ap(float x) {
    float y; asm("tanh.approx.f32 %0, %1;" : "=f"(y) : "f"(x)); return y;
}
__device__ __forceinline__ float sig_(float x) {
    return __fdividef(1.0f, 1.0f + __expf(-x));
}
// fp16 half-index for h value (batch b, unit k) in m16n8k16 A-fragment layout.
__device__ __forceinline__ int hidx16(int b, int k) {
    int kk = k >> 4, mt = b >> 4, r = b & 15, kl = k & 15;
    int lane = (r & 7) * 4 + ((kl & 7) >> 1);
    int w = ((kl >> 3) << 1) | (r >> 3);
    return (((kk * 4 + mt) * 32 + lane) * 4 + w) * 2 + (k & 1);
}

// ---------------------------------------------------------------------------
__global__ void zero_init_kernel(const int* __restrict__ sen_len) {
    int i = blockIdx.x * blockDim.x + threadIdx.x;
    if (i < (NBATCH * HID)) {          // both parities (as u32): 2*32768 halfs
        ((unsigned*)g_h0buf)[i] = 0u;
        ((unsigned*)g_h1buf)[i] = 0u;
    }
    if (i == 0) {
        g_ctr = 0u;
        int m = 1;
        for (int b = 0; b < NBATCH; b++) m = max(m, sen_len[b]);
        g_maxsl = m;
    }
}

// ---------------------------------------------------------------------------
// tf32 tensor-core GEMM: g_E0h[M][2048] = A[M][512] @ W[2048][512]^T + (b1+b2)
// ---------------------------------------------------------------------------
#define GSTR 36
#define GBUF (128 * GSTR)

__global__ __launch_bounds__(256) void gemm_e0_kernel(
    const float* __restrict__ A,
    const float* __restrict__ W,
    const float* __restrict__ bi1,
    const float* __restrict__ bi2,
    int M)
{
    extern __shared__ unsigned gsm[];
    unsigned* As = gsm;
    unsigned* Bs = gsm + 2 * GBUF;

    const int tid = threadIdx.x;
    const int lane = tid & 31;
    const int warp = tid >> 5;
    const int g = lane >> 2;
    const int tig = lane & 3;
    const int wm = warp & 1;
    const int wn = warp >> 1;
    const int m0 = blockIdx.y * 128;
    const int n0 = blockIdx.x * 128;

    float acc[4][4][4];
#pragma unroll
    for (int i = 0; i < 4; i++)
#pragma unroll
        for (int j = 0; j < 4; j++)
#pragma unroll
            for (int e = 0; e < 4; e++) acc[i][j][e] = 0.0f;

    int lrow[4], lc[4];
#pragma unroll
    for (int p = 0; p < 4; p++) {
        int id = tid + p * 256;
        lrow[p] = id >> 3;
        lc[p] = (id & 7) * 4;
    }

    {
#pragma unroll
        for (int p = 0; p < 4; p++) {
            int r = lrow[p], kc = lc[p];
            float4 va = make_float4(0.f, 0.f, 0.f, 0.f);
            if (m0 + r < M) va = *(const float4*)(A + (size_t)(m0 + r) * 512 + kc);
            *(uint4*)(As + r * GSTR + kc) = *(const uint4*)&va;
            float4 vb = *(const float4*)(W + (size_t)(n0 + r) * 512 + kc);
            *(uint4*)(Bs + r * GSTR + kc) = *(const uint4*)&vb;
        }
    }
    __syncthreads();

    float4 pa[4], pb[4];
    for (int it = 0; it < 16; it++) {
        int buf = it & 1;
        if (it < 15) {
            int k0 = (it + 1) * 32;
#pragma unroll
            for (int p = 0; p < 4; p++) {
                int r = lrow[p], kc = lc[p];
                pa[p] = make_float4(0.f, 0.f, 0.f, 0.f);
                if (m0 + r < M) pa[p] = *(const float4*)(A + (size_t)(m0 + r) * 512 + k0 + kc);
                pb[p] = *(const float4*)(W + (size_t)(n0 + r) * 512 + k0 + kc);
            }
        }
        const unsigned* Ab = As + buf * GBUF;
        const unsigned* Bb = Bs + buf * GBUF;
#pragma unroll
        for (int kk = 0; kk < 4; kk++) {
            int kb = kk * 8;
            unsigned af[4][4];
#pragma unroll
            for (int mf = 0; mf < 4; mf++) {
                int r = wm * 64 + mf * 16 + g;
                af[mf][0] = Ab[r * GSTR + kb + tig];
                af[mf][1] = Ab[(r + 8) * GSTR + kb + tig];
                af[mf][2] = Ab[r * GSTR + kb + tig + 4];
                af[mf][3] = Ab[(r + 8) * GSTR + kb + tig + 4];
            }
            unsigned bf[4][2];
#pragma unroll
            for (int nf = 0; nf < 4; nf++) {
                int n = wn * 32 + nf * 8 + g;
                bf[nf][0] = Bb[n * GSTR + kb + tig];
                bf[nf][1] = Bb[n * GSTR + kb + tig + 4];
            }
#pragma unroll
            for (int mf = 0; mf < 4; mf++)
#pragma unroll
                for (int nf = 0; nf < 4; nf++)
                    mma_tf32(acc[mf][nf], af[mf], bf[nf]);
        }
        if (it < 15) {
            unsigned* Ad = As + (buf ^ 1) * GBUF;
            unsigned* Bd = Bs + (buf ^ 1) * GBUF;
#pragma unroll
            for (int p = 0; p < 4; p++) {
                int r = lrow[p], kc = lc[p];
                *(uint4*)(Ad + r * GSTR + kc) = *(const uint4*)&pa[p];
                *(uint4*)(Bd + r * GSTR + kc) = *(const uint4*)&pb[p];
            }
        }
        __syncthreads();
    }

#pragma unroll
    for (int nf = 0; nf < 4; nf++) {
        int n = n0 + wn * 32 + nf * 8 + 2 * tig;
        float bb0 = bi1[n] + bi2[n];
        float bb1 = bi1[n + 1] + bi2[n + 1];
#pragma unroll
        for (int mf = 0; mf < 4; mf++) {
            int r = m0 + wm * 64 + mf * 16 + g;
            if (r < M) {
                __half2 v = __floats2half2_rn(acc[mf][nf][0] + bb0, acc[mf][nf][1] + bb1);
                *(__half2*)(g_E0h + (size_t)r * G4 + n) = v;
            }
            if (r + 8 < M) {
                __half2 v = __floats2half2_rn(acc[mf][nf][2] + bb0, acc[mf][nf][3] + bb1);
                *(__half2*)(g_E0h + (size_t)(r + 8) * G4 + n) = v;
            }
        }
    }
}

// ---------------------------------------------------------------------------
// Fused two-layer pipelined LSTM scan, batch-split tiling.
// 128 CTAs x 256 threads (1/SM). Block (ub = bid>>1, bh = bid&1) owns
// units [8ub, 8ub+8) (32 gate rows) x batches [32bh, 32bh+32).
// Warp w: ks = w>>1 (k-slice 128), ns = w&1 (rows ns*16+16).
//   per warp per GEMM: m32 x n16 x k128 (16 A-frag LDS.128, 32 HMMA).
//   B frags (Whh0, Wih1, Whh1) in 96 regs, loaded once.
// Staging: warp (ks,0) stages h0 k-slice, (ks,1) stages h1 k-slice
//   (8 KB each, only this block's batch half) -> 8 MB/step chip broadcast.
// Dynamic bound: loop t in [0, maxsl]; layer0 active t<maxsl, layer1 t>=1.
// Grid barrier: single-counter red.release + one-word acquire poll (proven).
// ---------------------------------------------------------------------------
__global__ __launch_bounds__(SCAN_THREADS) void lstm_fused_kernel(
    const int* __restrict__ src,
    const float* __restrict__ Whh0,
    const float* __restrict__ Wih1,
    const float* __restrict__ Whh1,
    const float* __restrict__ bih1,
    const float* __restrict__ bhh1,
    const int* __restrict__ sen_len,
    float* __restrict__ final_out)
{
    extern __shared__ unsigned ssm[];
    unsigned* sh_h0 = ssm;                     // 8192 u32 = 32 KB fp16 (this half)
    unsigned* sh_h1 = ssm + 8192;              // 8192 u32
    float* red0 = (float*)(ssm + 16384);       // [4][32][NPAD]
    float* red1 = red0 + 4 * 32 * NPAD;

    const int tid = threadIdx.x;
    const int lane = tid & 31;
    const int warp = tid >> 5;       // 0..7
    const int ks = warp >> 1;        // k-slice [128ks, 128ks+128)
    const int ns = warp & 1;         // row half
    const int g = lane >> 2;
    const int tig = lane & 3;
    const int ub = blockIdx.x >> 1;
    const int bh = blockIdx.x & 1;
    const int u0 = ub * 8;
    const unsigned nblk = gridDim.x;

    unsigned sh_base;
    asm("{ .reg .u64 t; cvta.to.shared.u64 t, %1; cvt.u32.u64 %0, t; }"
        : "=r"(sh_base) : "l"((void*)ssm));

    // ---- B fragments in registers (once): Whh0, Wih1, Whh1 ----
    unsigned breg0[8][2][2], bregI[8][2][2], bregU[8][2][2];
#pragma unroll
    for (int kkl = 0; kkl < 8; kkl++) {
#pragma unroll
        for (int nt = 0; nt < 2; nt++) {
            int n = ns * 16 + nt * 8 + g;
            size_t row = (size_t)((n & 3) * 512 + u0 + (n >> 2)) * 512
                       + ks * 128 + kkl * 16;
            {
                const float* wr = Whh0 + row;
                __half2 h0 = __floats2half2_rn(wr[2 * tig], wr[2 * tig + 1]);
                __half2 h1 = __floats2half2_rn(wr[2 * tig + 8], wr[2 * tig + 9]);
                breg0[kkl][nt][0] = *(unsigned*)&h0;
                breg0[kkl][nt][1] = *(unsigned*)&h1;
            }
            {
                const float* wr = Wih1 + row;
                __half2 h0 = __floats2half2_rn(wr[2 * tig], wr[2 * tig + 1]);
                __half2 h1 = __floats2half2_rn(wr[2 * tig + 8], wr[2 * tig + 9]);
                bregI[kkl][nt][0] = *(unsigned*)&h0;
                bregI[kkl][nt][1] = *(unsigned*)&h1;
            }
            {
                const float* wr = Whh1 + row;
                __half2 h0 = __floats2half2_rn(wr[2 * tig], wr[2 * tig + 1]);
                __half2 h1 = __floats2half2_rn(wr[2 * tig + 8], wr[2 * tig + 9]);
                bregU[kkl][nt][0] = *(unsigned*)&h0;
                bregU[kkl][nt][1] = *(unsigned*)&h1;
            }
        }
    }

    // ---- cell-phase mapping: thread = (unit u_loc, batch b_loc) ----
    const int u_loc = tid >> 5;          // 0..7
    const int b_loc = lane;              // 0..31
    const int b_glob = bh * 32 + b_loc;
    const int u_glob = u0 + u_loc;

    float bsum[4];
#pragma unroll
    for (int gt = 0; gt < 4; gt++)
        bsum[gt] = bih1[gt * 512 + u_glob] + bhh1[gt * 512 + u_glob];

    float c_l0 = 0.f, c_l1 = 0.f;
    const int sl = sen_len[b_glob];
    const int maxsl = g_maxsl;
    const int hi = hidx16(b_glob, u_glob);

    for (int t = 0; t <= maxsl; t++) {
        const bool do_l0 = (t < maxsl);
        const bool do_l1 = (t >= 1);

        // ---- stage: warp (ks,0) -> h0[t-1] slice; (ks,1) -> h1[t-2] slice ----
        {
            const uint4* gs = (const uint4*)(ns == 0 ? g_h0buf[(t + 1) & 1]
                                                     : g_h1buf[t & 1]);
            unsigned dstbase = sh_base + (ns ? 32768u : 0u);
#pragma unroll
            for (int i = 0; i < 16; i++) {
                int kk = ks * 8 + (i >> 1);
                int io = i & 1;
                int gidx = (kk * 4 + 2 * bh + io) * 32 + lane;
                int didx = (kk * 2 + io) * 32 + lane;
                cp16(dstbase + (unsigned)didx * 16, gs + gidx);
            }
            asm volatile("cp.async.commit_group;");
        }

        // ---- prefetch layer0 cell input (E0 gather; overlaps cp.async) ----
        float p[4];
        {
            int tt = do_l0 ? t : 0;
            int r = src[tt * NBATCH + b_glob];
            const __half* e = g_E0h + (size_t)r * G4 + u_glob;
#pragma unroll
            for (int gt = 0; gt < 4; gt++) p[gt] = __half2float(e[gt * 512]);
        }

        asm volatile("cp.async.wait_group 0;" ::: "memory");
        __syncthreads();   // staging is split across warps

        // ---- mma: 3 GEMMs, m32 x n16 x k128 per warp ----
        {
            float acc0[2][2][4], acc1[2][2][4];
#pragma unroll
            for (int mt2 = 0; mt2 < 2; mt2++)
#pragma unroll
                for (int nt = 0; nt < 2; nt++)
#pragma unroll
                    for (int e = 0; e < 4; e++) { acc0[mt2][nt][e] = 0.f; acc1[mt2][nt][e] = 0.f; }

#pragma unroll
            for (int kkl = 0; kkl < 8; kkl++) {
                int base = (ks * 8 + kkl) * 2;
#pragma unroll
                for (int mt2 = 0; mt2 < 2; mt2++) {
                    uint4 a0 = *(const uint4*)(sh_h0 + ((base + mt2) * 32 + lane) * 4);
                    mma_f16(acc0[mt2][0], (const unsigned*)&a0, breg0[kkl][0]);
                    mma_f16(acc0[mt2][1], (const unsigned*)&a0, breg0[kkl][1]);
                    mma_f16(acc1[mt2][0], (const unsigned*)&a0, bregI[kkl][0]);
                    mma_f16(acc1[mt2][1], (const unsigned*)&a0, bregI[kkl][1]);
                    uint4 a1 = *(const uint4*)(sh_h1 + ((base + mt2) * 32 + lane) * 4);
                    mma_f16(acc1[mt2][0], (const unsigned*)&a1, bregU[kkl][0]);
                    mma_f16(acc1[mt2][1], (const unsigned*)&a1, bregU[kkl][1]);
                }
            }

            // ---- store k-partials: red[ks][m_loc][n] ----
#pragma unroll
            for (int mt2 = 0; mt2 < 2; mt2++)
#pragma unroll
                for (int nt = 0; nt < 2; nt++) {
                    int m_loc = mt2 * 16 + g;
                    int col = ns * 16 + nt * 8 + 2 * tig;
                    float* rp0 = &red0[(ks * 32 + m_loc) * NPAD + col];
                    *(float2*)rp0 = make_float2(acc0[mt2][nt][0], acc0[mt2][nt][1]);
                    *(float2*)(rp0 + 8 * NPAD) = make_float2(acc0[mt2][nt][2], acc0[mt2][nt][3]);
                    float* rp1 = &red1[(ks * 32 + m_loc) * NPAD + col];
                    *(float2*)rp1 = make_float2(acc1[mt2][nt][0], acc1[mt2][nt][1]);
                    *(float2*)(rp1 + 8 * NPAD) = make_float2(acc1[mt2][nt][2], acc1[mt2][nt][3]);
                }
        }
        __syncthreads();

        // ---- layer0 cell: h_l0[t] ----
        if (do_l0) {
            float z[4];
#pragma unroll
            for (int gt = 0; gt < 4; gt++) z[gt] = p[gt];
#pragma unroll
            for (int w = 0; w < 4; w++) {
                float4 v = *(const float4*)&red0[(w * 32 + b_loc) * NPAD + u_loc * 4];
                z[0] += v.x; z[1] += v.y; z[2] += v.z; z[3] += v.w;
            }
            float ig = sig_(z[0]), fg = sig_(z[1]), gg = tanh_ap(z[2]), og = sig_(z[3]);
            c_l0 = fg * c_l0 + ig * gg;
            float hn = og * tanh_ap(c_l0);
            g_h0buf[t & 1][hi] = __float2half_rn(hn);
        }

        // ---- layer1 cell: h_l1[t-1] ----
        if (do_l1) {
            float z[4];
#pragma unroll
            for (int gt = 0; gt < 4; gt++) z[gt] = bsum[gt];
#pragma unroll
            for (int w = 0; w < 4; w++) {
                float4 v = *(const float4*)&red1[(w * 32 + b_loc) * NPAD + u_loc * 4];
                z[0] += v.x; z[1] += v.y; z[2] += v.z; z[3] += v.w;
            }
            float ig = sig_(z[0]), fg = sig_(z[1]), gg = tanh_ap(z[2]), og = sig_(z[3]);
            c_l1 = fg * c_l1 + ig * gg;
            float hn = og * tanh_ap(c_l1);
            g_h1buf[(t - 1) & 1][hi] = __float2half_rn(hn);
            if (t == sl) final_out[b_glob * HID + u_glob] = hn;
        }

        // ---- grid barrier (single counter, release/acquire) ----
        __syncthreads();   // all h stores issued block-wide
        if (tid == 0) {
            asm volatile("red.release.gpu.global.add.u32 [%0], 1;"
                         :: "l"(&g_ctr) : "memory");
            unsigned tgt = nblk * (unsigned)(t + 1);
            while (ld_acq(&g_ctr) < tgt) { }
        }
        __syncthreads();
    }
}

// ---------------------------------------------------------------------------
extern "C" void kernel_launch(void* const* d_in, const int* in_sizes, int n_in,
                              void* d_out, int out_size)
{
    const int*   src       = (const int*)  d_in[0];
    const int*   sen_len   = (const int*)  d_in[1];
    const float* emb_table = (const float*)d_in[2];
    const float* Wih0      = (const float*)d_in[3];
    const float* Whh0      = (const float*)d_in[4];
    const float* bih0      = (const float*)d_in[5];
    const float* bhh0      = (const float*)d_in[6];
    const float* Wih1      = (const float*)d_in[7];
    const float* Whh1      = (const float*)d_in[8];
    const float* bih1      = (const float*)d_in[9];
    const float* bhh1      = (const float*)d_in[10];
    float* out = (float*)d_out;

    const size_t gemm_smem = (size_t)4 * GBUF * sizeof(unsigned);        // 73728 B
    const size_t scan_smem =
        (size_t)(16384 + 2 * 4 * 32 * NPAD) * sizeof(unsigned);          // 102400 B
    cudaFuncSetAttribute(gemm_e0_kernel,
                         cudaFuncAttributeMaxDynamicSharedMemorySize, (int)gemm_smem);
    cudaFuncSetAttribute(lstm_fused_kernel,
                         cudaFuncAttributeMaxDynamicSharedMemorySize, (int)scan_smem);

    // Phase 0: E0 = emb_table @ Wih0^T + (bih0+bhh0)   (10000 x 2048, fp16)
    {
        dim3 grid(G4 / 128, (NVOCAB + 127) / 128);
        gemm_e0_kernel<<<grid, 256, gemm_smem>>>(emb_table, Wih0, bih0, bhh0, NVOCAB);
    }

    // Phase 1: fused two-layer pipelined scan (maxsl+1 iterations)
    zero_init_kernel<<<128, 512>>>(sen_len);
    lstm_fused_kernel<<<SCAN_BLOCKS, SCAN_THREADS, scan_smem>>>(
        src, Whh0, Wih1, Whh1, bih1, bhh1, sen_len, out);
}

// round 11
// speedup vs baseline: 3.8002x; 1.1002x over previous
#include <cuda_runtime.h>
#include <cuda_fp16.h>
#include <math.h>
#include <stdint.h>

// Problem constants
#define T_LEN 512
#define NBATCH 64
#define HID 512
#define G4 2048          // 4*HID
#define NVOCAB 10000

#define SCAN_BLOCKS 128
#define SCAN_THREADS 256
#define NPAD 36          // red buffer row stride (floats)

// -------- device scratch --------
__device__ __align__(16) __half g_E0h[(size_t)NVOCAB * G4];   // emb @ Wih0^T + b0 (fp16)
__device__ __align__(16) __half g_h0buf[2][NBATCH * HID];     // layer0 h ping-pong, frag layout
__device__ __align__(16) __half g_h1buf[2][NBATCH * HID];     // layer1 h ping-pong, frag layout
__device__ unsigned g_ctrs[2][64];                             // per-half barrier counters (256B apart)
__device__ int g_maxsl2[2];                                    // per-half max(sen_len)

// ---------------- helpers ----------------
__device__ __forceinline__ void mma_tf32(float* c, const unsigned* a, const unsigned* b) {
    asm("mma.sync.aligned.m16n8k8.row.col.f32.tf32.tf32.f32 "
        "{%0,%1,%2,%3}, {%4,%5,%6,%7}, {%8,%9}, {%0,%1,%2,%3};"
        : "+f"(c[0]), "+f"(c[1]), "+f"(c[2]), "+f"(c[3])
        : "r"(a[0]), "r"(a[1]), "r"(a[2]), "r"(a[3]), "r"(b[0]), "r"(b[1]));
}
__device__ __forceinline__ void mma_f16(float* c, const unsigned* a, const unsigned* b) {
    asm("mma.sync.aligned.m16n8k16.row.col.f32.f16.f16.f32 "
        "{%0,%1,%2,%3}, {%4,%5,%6,%7}, {%8,%9}, {%0,%1,%2,%3};"
        : "+f"(c[0]), "+f"(c[1]), "+f"(c[2]), "+f"(c[3])
        : "r"(a[0]), "r"(a[1]), "r"(a[2]), "r"(a[3]), "r"(b[0]), "r"(b[1]));
}
__device__ __forceinline__ unsigned ld_acq(const unsigned* p) {
    unsigned v; asm volatile("ld.acquire.gpu.global.u32 %0, [%1];" : "=r"(v) : "l"(p)); return v;
}
__device__ __forceinline__ void cp16(unsigned sdst, const void* gsrc) {
    asm volatile("cp.async.cg.shared.global [%0], [%1], 16;" :: "r"(sdst), "l"(gsrc));
}
__device__ __forceinline__ float tanh_ap(float x) {
    float y; asm("tanh.approx.f32 %0, %1;" : "=f"(y) : "f"(x)); return y;
}
// sigmoid via tanh: sig(x) = 0.5*tanh(x/2) + 0.5  (1 MUFU instead of EX2+RCP)
__device__ __forceinline__ float sig_(float x) {
    return fmaf(0.5f, tanh_ap(0.5f * x), 0.5f);
}
// fp16 half-index for h value (batch b, unit k) in m16n8k16 A-fragment layout.
__device__ __forceinline__ int hidx16(int b, int k) {
    int kk = k >> 4, mt = b >> 4, r = b & 15, kl = k & 15;
    int lane = (r & 7) * 4 + ((kl & 7) >> 1);
    int w = ((kl >> 3) << 1) | (r >> 3);
    return (((kk * 4 + mt) * 32 + lane) * 4 + w) * 2 + (k & 1);
}

// ---------------------------------------------------------------------------
__global__ void zero_init_kernel(const int* __restrict__ sen_len) {
    int i = blockIdx.x * blockDim.x + threadIdx.x;
    if (i < (NBATCH * HID)) {          // both parities (as u32): 2*32768 halfs
        ((unsigned*)g_h0buf)[i] = 0u;
        ((unsigned*)g_h1buf)[i] = 0u;
    }
    if (i < 2 * 64) ((unsigned*)g_ctrs)[i] = 0u;
    if (i < 2) {
        int m = 1;
        for (int b = 0; b < 32; b++) m = max(m, sen_len[i * 32 + b]);
        g_maxsl2[i] = m;
    }
}

// ---------------------------------------------------------------------------
// tf32 tensor-core GEMM: g_E0h[M][2048] = A[M][512] @ W[2048][512]^T + (b1+b2)
// ---------------------------------------------------------------------------
#define GSTR 36
#define GBUF (128 * GSTR)

__global__ __launch_bounds__(256) void gemm_e0_kernel(
    const float* __restrict__ A,
    const float* __restrict__ W,
    const float* __restrict__ bi1,
    const float* __restrict__ bi2,
    int M)
{
    extern __shared__ unsigned gsm[];
    unsigned* As = gsm;
    unsigned* Bs = gsm + 2 * GBUF;

    const int tid = threadIdx.x;
    const int lane = tid & 31;
    const int warp = tid >> 5;
    const int g = lane >> 2;
    const int tig = lane & 3;
    const int wm = warp & 1;
    const int wn = warp >> 1;
    const int m0 = blockIdx.y * 128;
    const int n0 = blockIdx.x * 128;

    float acc[4][4][4];
#pragma unroll
    for (int i = 0; i < 4; i++)
#pragma unroll
        for (int j = 0; j < 4; j++)
#pragma unroll
            for (int e = 0; e < 4; e++) acc[i][j][e] = 0.0f;

    int lrow[4], lc[4];
#pragma unroll
    for (int p = 0; p < 4; p++) {
        int id = tid + p * 256;
        lrow[p] = id >> 3;
        lc[p] = (id & 7) * 4;
    }

    {
#pragma unroll
        for (int p = 0; p < 4; p++) {
            int r = lrow[p], kc = lc[p];
            float4 va = make_float4(0.f, 0.f, 0.f, 0.f);
            if (m0 + r < M) va = *(const float4*)(A + (size_t)(m0 + r) * 512 + kc);
            *(uint4*)(As + r * GSTR + kc) = *(const uint4*)&va;
            float4 vb = *(const float4*)(W + (size_t)(n0 + r) * 512 + kc);
            *(uint4*)(Bs + r * GSTR + kc) = *(const uint4*)&vb;
        }
    }
    __syncthreads();

    float4 pa[4], pb[4];
    for (int it = 0; it < 16; it++) {
        int buf = it & 1;
        if (it < 15) {
            int k0 = (it + 1) * 32;
#pragma unroll
            for (int p = 0; p < 4; p++) {
                int r = lrow[p], kc = lc[p];
                pa[p] = make_float4(0.f, 0.f, 0.f, 0.f);
                if (m0 + r < M) pa[p] = *(const float4*)(A + (size_t)(m0 + r) * 512 + k0 + kc);
                pb[p] = *(const float4*)(W + (size_t)(n0 + r) * 512 + k0 + kc);
            }
        }
        const unsigned* Ab = As + buf * GBUF;
        const unsigned* Bb = Bs + buf * GBUF;
#pragma unroll
        for (int kk = 0; kk < 4; kk++) {
            int kb = kk * 8;
            unsigned af[4][4];
#pragma unroll
            for (int mf = 0; mf < 4; mf++) {
                int r = wm * 64 + mf * 16 + g;
                af[mf][0] = Ab[r * GSTR + kb + tig];
                af[mf][1] = Ab[(r + 8) * GSTR + kb + tig];
                af[mf][2] = Ab[r * GSTR + kb + tig + 4];
                af[mf][3] = Ab[(r + 8) * GSTR + kb + tig + 4];
            }
            unsigned bf[4][2];
#pragma unroll
            for (int nf = 0; nf < 4; nf++) {
                int n = wn * 32 + nf * 8 + g;
                bf[nf][0] = Bb[n * GSTR + kb + tig];
                bf[nf][1] = Bb[n * GSTR + kb + tig + 4];
            }
#pragma unroll
            for (int mf = 0; mf < 4; mf++)
#pragma unroll
                for (int nf = 0; nf < 4; nf++)
                    mma_tf32(acc[mf][nf], af[mf], bf[nf]);
        }
        if (it < 15) {
            unsigned* Ad = As + (buf ^ 1) * GBUF;
            unsigned* Bd = Bs + (buf ^ 1) * GBUF;
#pragma unroll
            for (int p = 0; p < 4; p++) {
                int r = lrow[p], kc = lc[p];
                *(uint4*)(Ad + r * GSTR + kc) = *(const uint4*)&pa[p];
                *(uint4*)(Bd + r * GSTR + kc) = *(const uint4*)&pb[p];
            }
        }
        __syncthreads();
    }

#pragma unroll
    for (int nf = 0; nf < 4; nf++) {
        int n = n0 + wn * 32 + nf * 8 + 2 * tig;
        float bb0 = bi1[n] + bi2[n];
        float bb1 = bi1[n + 1] + bi2[n + 1];
#pragma unroll
        for (int mf = 0; mf < 4; mf++) {
            int r = m0 + wm * 64 + mf * 16 + g;
            if (r < M) {
                __half2 v = __floats2half2_rn(acc[mf][nf][0] + bb0, acc[mf][nf][1] + bb1);
                *(__half2*)(g_E0h + (size_t)r * G4 + n) = v;
            }
            if (r + 8 < M) {
                __half2 v = __floats2half2_rn(acc[mf][nf][2] + bb0, acc[mf][nf][3] + bb1);
                *(__half2*)(g_E0h + (size_t)(r + 8) * G4 + n) = v;
            }
        }
    }
}

// ---------------------------------------------------------------------------
// Fused two-layer pipelined LSTM scan, batch-split tiling, decoupled groups.
// 128 CTAs x 256 threads (1/SM). Block (ub = bid>>1, bh = bid&1) owns
// units [8ub, 8ub+8) (32 gate rows) x batches [32bh, 32bh+32).
// The two batch halves are COMPLETELY independent: each has its own barrier
// counter (separate L2 lines) and its own loop bound max(sen_len[half]).
// Warp w: ks = w>>1 (k-slice 128), ns = w&1 (rows ns*16+16).
// E0 gather for step t+1 is prefetched between barrier arrive and poll.
// ---------------------------------------------------------------------------
__global__ __launch_bounds__(SCAN_THREADS) void lstm_fused_kernel(
    const int* __restrict__ src,
    const float* __restrict__ Whh0,
    const float* __restrict__ Wih1,
    const float* __restrict__ Whh1,
    const float* __restrict__ bih1,
    const float* __restrict__ bhh1,
    const int* __restrict__ sen_len,
    float* __restrict__ final_out)
{
    extern __shared__ unsigned ssm[];
    unsigned* sh_h0 = ssm;                     // 8192 u32 = 32 KB fp16 (this half)
    unsigned* sh_h1 = ssm + 8192;              // 8192 u32
    float* red0 = (float*)(ssm + 16384);       // [4][32][NPAD]
    float* red1 = red0 + 4 * 32 * NPAD;

    const int tid = threadIdx.x;
    const int lane = tid & 31;
    const int warp = tid >> 5;       // 0..7
    const int ks = warp >> 1;        // k-slice [128ks, 128ks+128)
    const int ns = warp & 1;         // row half
    const int g = lane >> 2;
    const int tig = lane & 3;
    const int ub = blockIdx.x >> 1;
    const int bh = blockIdx.x & 1;
    const int u0 = ub * 8;

    unsigned sh_base;
    asm("{ .reg .u64 t; cvta.to.shared.u64 t, %1; cvt.u32.u64 %0, t; }"
        : "=r"(sh_base) : "l"((void*)ssm));

    // ---- B fragments in registers (once): Whh0, Wih1, Whh1 ----
    unsigned breg0[8][2][2], bregI[8][2][2], bregU[8][2][2];
#pragma unroll
    for (int kkl = 0; kkl < 8; kkl++) {
#pragma unroll
        for (int nt = 0; nt < 2; nt++) {
            int n = ns * 16 + nt * 8 + g;
            size_t row = (size_t)((n & 3) * 512 + u0 + (n >> 2)) * 512
                       + ks * 128 + kkl * 16;
            {
                const float* wr = Whh0 + row;
                __half2 h0 = __floats2half2_rn(wr[2 * tig], wr[2 * tig + 1]);
                __half2 h1 = __floats2half2_rn(wr[2 * tig + 8], wr[2 * tig + 9]);
                breg0[kkl][nt][0] = *(unsigned*)&h0;
                breg0[kkl][nt][1] = *(unsigned*)&h1;
            }
            {
                const float* wr = Wih1 + row;
                __half2 h0 = __floats2half2_rn(wr[2 * tig], wr[2 * tig + 1]);
                __half2 h1 = __floats2half2_rn(wr[2 * tig + 8], wr[2 * tig + 9]);
                bregI[kkl][nt][0] = *(unsigned*)&h0;
                bregI[kkl][nt][1] = *(unsigned*)&h1;
            }
            {
                const float* wr = Whh1 + row;
                __half2 h0 = __floats2half2_rn(wr[2 * tig], wr[2 * tig + 1]);
                __half2 h1 = __floats2half2_rn(wr[2 * tig + 8], wr[2 * tig + 9]);
                bregU[kkl][nt][0] = *(unsigned*)&h0;
                bregU[kkl][nt][1] = *(unsigned*)&h1;
            }
        }
    }

    // ---- cell-phase mapping: thread = (unit u_loc, batch b_loc) ----
    const int u_loc = tid >> 5;          // 0..7
    const int b_loc = lane;              // 0..31
    const int b_glob = bh * 32 + b_loc;
    const int u_glob = u0 + u_loc;

    float bsum[4];
#pragma unroll
    for (int gt = 0; gt < 4; gt++)
        bsum[gt] = bih1[gt * 512 + u_glob] + bhh1[gt * 512 + u_glob];

    float c_l0 = 0.f, c_l1 = 0.f;
    const int sl = sen_len[b_glob];
    const int maxsl = g_maxsl2[bh];
    const int hi = hidx16(b_glob, u_glob);
    unsigned* ctr = &g_ctrs[bh][0];

    // ---- initial E0 prefetch (t = 0) ----
    float p[4];
    {
        int r = src[b_glob];
        const __half* e = g_E0h + (size_t)r * G4 + u_glob;
#pragma unroll
        for (int gt = 0; gt < 4; gt++) p[gt] = __half2float(e[gt * 512]);
    }

    for (int t = 0; t <= maxsl; t++) {
        const bool do_l0 = (t < maxsl);
        const bool do_l1 = (t >= 1);

        // ---- stage: warp (ks,0) -> h0[t-1] slice; (ks,1) -> h1[t-2] slice ----
        {
            const uint4* gs = (const uint4*)(ns == 0 ? g_h0buf[(t + 1) & 1]
                                                     : g_h1buf[t & 1]);
            unsigned dstbase = sh_base + (ns ? 32768u : 0u);
#pragma unroll
            for (int i = 0; i < 16; i++) {
                int kk = ks * 8 + (i >> 1);
                int io = i & 1;
                int gidx = (kk * 4 + 2 * bh + io) * 32 + lane;
                int didx = (kk * 2 + io) * 32 + lane;
                cp16(dstbase + (unsigned)didx * 16, gs + gidx);
            }
            asm volatile("cp.async.commit_group;");
        }

        asm volatile("cp.async.wait_group 0;" ::: "memory");
        __syncthreads();   // staging is split across warps

        // ---- mma: 3 GEMMs, m32 x n16 x k128 per warp ----
        {
            float acc0[2][2][4], acc1[2][2][4];
#pragma unroll
            for (int mt2 = 0; mt2 < 2; mt2++)
#pragma unroll
                for (int nt = 0; nt < 2; nt++)
#pragma unroll
                    for (int e = 0; e < 4; e++) { acc0[mt2][nt][e] = 0.f; acc1[mt2][nt][e] = 0.f; }

#pragma unroll
            for (int kkl = 0; kkl < 8; kkl++) {
                int base = (ks * 8 + kkl) * 2;
#pragma unroll
                for (int mt2 = 0; mt2 < 2; mt2++) {
                    uint4 a0 = *(const uint4*)(sh_h0 + ((base + mt2) * 32 + lane) * 4);
                    mma_f16(acc0[mt2][0], (const unsigned*)&a0, breg0[kkl][0]);
                    mma_f16(acc0[mt2][1], (const unsigned*)&a0, breg0[kkl][1]);
                    mma_f16(acc1[mt2][0], (const unsigned*)&a0, bregI[kkl][0]);
                    mma_f16(acc1[mt2][1], (const unsigned*)&a0, bregI[kkl][1]);
                    uint4 a1 = *(const uint4*)(sh_h1 + ((base + mt2) * 32 + lane) * 4);
                    mma_f16(acc1[mt2][0], (const unsigned*)&a1, bregU[kkl][0]);
                    mma_f16(acc1[mt2][1], (const unsigned*)&a1, bregU[kkl][1]);
                }
            }

            // ---- store k-partials: red[ks][m_loc][n] ----
#pragma unroll
            for (int mt2 = 0; mt2 < 2; mt2++)
#pragma unroll
                for (int nt = 0; nt < 2; nt++) {
                    int m_loc = mt2 * 16 + g;
                    int col = ns * 16 + nt * 8 + 2 * tig;
                    float* rp0 = &red0[(ks * 32 + m_loc) * NPAD + col];
                    *(float2*)rp0 = make_float2(acc0[mt2][nt][0], acc0[mt2][nt][1]);
                    *(float2*)(rp0 + 8 * NPAD) = make_float2(acc0[mt2][nt][2], acc0[mt2][nt][3]);
                    float* rp1 = &red1[(ks * 32 + m_loc) * NPAD + col];
                    *(float2*)rp1 = make_float2(acc1[mt2][nt][0], acc1[mt2][nt][1]);
                    *(float2*)(rp1 + 8 * NPAD) = make_float2(acc1[mt2][nt][2], acc1[mt2][nt][3]);
                }
        }
        __syncthreads();

        // ---- layer0 cell: h_l0[t] ----
        if (do_l0) {
            float z[4];
#pragma unroll
            for (int gt = 0; gt < 4; gt++) z[gt] = p[gt];
#pragma unroll
            for (int w = 0; w < 4; w++) {
                float4 v = *(const float4*)&red0[(w * 32 + b_loc) * NPAD + u_loc * 4];
                z[0] += v.x; z[1] += v.y; z[2] += v.z; z[3] += v.w;
            }
            float ig = sig_(z[0]), fg = sig_(z[1]), gg = tanh_ap(z[2]), og = sig_(z[3]);
            c_l0 = fg * c_l0 + ig * gg;
            float hn = og * tanh_ap(c_l0);
            g_h0buf[t & 1][hi] = __float2half_rn(hn);
        }

        // ---- layer1 cell: h_l1[t-1] ----
        if (do_l1) {
            float z[4];
#pragma unroll
            for (int gt = 0; gt < 4; gt++) z[gt] = bsum[gt];
#pragma unroll
            for (int w = 0; w < 4; w++) {
                float4 v = *(const float4*)&red1[(w * 32 + b_loc) * NPAD + u_loc * 4];
                z[0] += v.x; z[1] += v.y; z[2] += v.z; z[3] += v.w;
            }
            float ig = sig_(z[0]), fg = sig_(z[1]), gg = tanh_ap(z[2]), og = sig_(z[3]);
            c_l1 = fg * c_l1 + ig * gg;
            float hn = og * tanh_ap(c_l1);
            g_h1buf[(t - 1) & 1][hi] = __float2half_rn(hn);
            if (t == sl) final_out[b_glob * HID + u_glob] = hn;
        }

        // ---- grid barrier (per-half counter) + E0 prefetch overlap ----
        __syncthreads();   // all h stores issued block-wide
        if (tid == 0) {
            asm volatile("red.release.gpu.global.add.u32 [%0], 1;"
                         :: "l"(ctr) : "memory");
        }
        // prefetch E0 for step t+1 while tid0 polls (independent of h)
        {
            int tt = (t + 1 < maxsl) ? (t + 1) : 0;
            int r = src[tt * NBATCH + b_glob];
            const __half* e = g_E0h + (size_t)r * G4 + u_glob;
#pragma unroll
            for (int gt = 0; gt < 4; gt++) p[gt] = __half2float(e[gt * 512]);
        }
        if (tid == 0) {
            unsigned tgt = 64u * (unsigned)(t + 1);
            while (ld_acq(ctr) < tgt) { }
        }
        __syncthreads();
    }
}

// ---------------------------------------------------------------------------
extern "C" void kernel_launch(void* const* d_in, const int* in_sizes, int n_in,
                              void* d_out, int out_size)
{
    const int*   src       = (const int*)  d_in[0];
    const int*   sen_len   = (const int*)  d_in[1];
    const float* emb_table = (const float*)d_in[2];
    const float* Wih0      = (const float*)d_in[3];
    const float* Whh0      = (const float*)d_in[4];
    const float* bih0      = (const float*)d_in[5];
    const float* bhh0      = (const float*)d_in[6];
    const float* Wih1      = (const float*)d_in[7];
    const float* Whh1      = (const float*)d_in[8];
    const float* bih1      = (const float*)d_in[9];
    const float* bhh1      = (const float*)d_in[10];
    float* out = (float*)d_out;

    const size_t gemm_smem = (size_t)4 * GBUF * sizeof(unsigned);        // 73728 B
    const size_t scan_smem =
        (size_t)(16384 + 2 * 4 * 32 * NPAD) * sizeof(unsigned);          // 102400 B
    cudaFuncSetAttribute(gemm_e0_kernel,
                         cudaFuncAttributeMaxDynamicSharedMemorySize, (int)gemm_smem);
    cudaFuncSetAttribute(lstm_fused_kernel,
                         cudaFuncAttributeMaxDynamicSharedMemorySize, (int)scan_smem);

    // Phase 0: E0 = emb_table @ Wih0^T + (bih0+bhh0)   (10000 x 2048, fp16)
    {
        dim3 grid(G4 / 128, (NVOCAB + 127) / 128);
        gemm_e0_kernel<<<grid, 256, gemm_smem>>>(emb_table, Wih0, bih0, bhh0, NVOCAB);
    }

    // Phase 1: fused two-layer pipelined scan, decoupled batch halves
    zero_init_kernel<<<128, 512>>>(sen_len);
    lstm_fused_kernel<<<SCAN_BLOCKS, SCAN_THREADS, scan_smem>>>(
        src, Whh0, Wih1, Whh1, bih1, bhh1, sen_len, out);
}

// round 12
// speedup vs baseline: 3.8952x; 1.0250x over previous
#include <cuda_runtime.h>
#include <cuda_fp16.h>
#include <math.h>
#include <stdint.h>

// Problem constants
#define T_LEN 512
#define NBATCH 64
#define HID 512
#define G4 2048          // 4*HID
#define NVOCAB 10000

#define SCAN_BLOCKS 128
#define SCAN_THREADS 256
#define NPAD 36          // red buffer row stride (floats)

// -------- device scratch --------
__device__ __align__(16) __half g_E0h[(size_t)NVOCAB * G4];   // emb @ Wih0^T + b0 (fp16)
__device__ __align__(16) __half g_h0buf[2][NBATCH * HID];     // layer0 h ping-pong, frag layout
__device__ __align__(16) __half g_h1buf[2][NBATCH * HID];     // layer1 h ping-pong, frag layout
__device__ unsigned g_ctrs[2][64];                             // per-half barrier counters (256B apart)
__device__ int g_maxsl2[2];                                    // per-half max(sen_len)

// ---------------- helpers ----------------
__device__ __forceinline__ void mma_tf32(float* c, const unsigned* a, const unsigned* b) {
    asm("mma.sync.aligned.m16n8k8.row.col.f32.tf32.tf32.f32 "
        "{%0,%1,%2,%3}, {%4,%5,%6,%7}, {%8,%9}, {%0,%1,%2,%3};"
        : "+f"(c[0]), "+f"(c[1]), "+f"(c[2]), "+f"(c[3])
        : "r"(a[0]), "r"(a[1]), "r"(a[2]), "r"(a[3]), "r"(b[0]), "r"(b[1]));
}
__device__ __forceinline__ void mma_f16(float* c, const unsigned* a, const unsigned* b) {
    asm("mma.sync.aligned.m16n8k16.row.col.f32.f16.f16.f32 "
        "{%0,%1,%2,%3}, {%4,%5,%6,%7}, {%8,%9}, {%0,%1,%2,%3};"
        : "+f"(c[0]), "+f"(c[1]), "+f"(c[2]), "+f"(c[3])
        : "r"(a[0]), "r"(a[1]), "r"(a[2]), "r"(a[3]), "r"(b[0]), "r"(b[1]));
}
__device__ __forceinline__ unsigned ld_acq(const unsigned* p) {
    unsigned v; asm volatile("ld.acquire.gpu.global.u32 %0, [%1];" : "=r"(v) : "l"(p)); return v;
}
__device__ __forceinline__ void cp16(unsigned sdst, const void* gsrc) {
    asm volatile("cp.async.cg.shared.global [%0], [%1], 16;" :: "r"(sdst), "l"(gsrc));
}
__device__ __forceinline__ float tanh_ap(float x) {
    float y; asm("tanh.approx.f32 %0, %1;" : "=f"(y) : "f"(x)); return y;
}
// sigmoid via tanh: sig(x) = 0.5*tanh(x/2) + 0.5  (1 MUFU instead of EX2+RCP)
__device__ __forceinline__ float sig_(float x) {
    return fmaf(0.5f, tanh_ap(0.5f * x), 0.5f);
}
// fp16 half-index for h value (batch b, unit k) in m16n8k16 A-fragment layout.
__device__ __forceinline__ int hidx16(int b, int k) {
    int kk = k >> 4, mt = b >> 4, r = b & 15, kl = k & 15;
    int lane = (r & 7) * 4 + ((kl & 7) >> 1);
    int w = ((kl >> 3) << 1) | (r >> 3);
    return (((kk * 4 + mt) * 32 + lane) * 4 + w) * 2 + (k & 1);
}

// ---------------------------------------------------------------------------
__global__ void zero_init_kernel(const int* __restrict__ sen_len) {
    int i = blockIdx.x * blockDim.x + threadIdx.x;
    if (i < (NBATCH * HID)) {          // both parities (as u32): 2*32768 halfs
        ((unsigned*)g_h0buf)[i] = 0u;
        ((unsigned*)g_h1buf)[i] = 0u;
    }
    if (i < 2 * 64) ((unsigned*)g_ctrs)[i] = 0u;
    if (i < 2) {
        int m = 1;
        for (int b = 0; b < 32; b++) m = max(m, sen_len[i * 32 + b]);
        g_maxsl2[i] = m;
    }
}

// ---------------------------------------------------------------------------
// tf32 tensor-core GEMM: g_E0h[M][2048] = A[M][512] @ W[2048][512]^T + (b1+b2)
// 2 CTAs/SM (regs<=128, 2x72KB smem fits 228KB) to hide smem/mma latency.
// ---------------------------------------------------------------------------
#define GSTR 36
#define GBUF (128 * GSTR)

__global__ __launch_bounds__(256, 2) void gemm_e0_kernel(
    const float* __restrict__ A,
    const float* __restrict__ W,
    const float* __restrict__ bi1,
    const float* __restrict__ bi2,
    int M)
{
    extern __shared__ unsigned gsm[];
    unsigned* As = gsm;
    unsigned* Bs = gsm + 2 * GBUF;

    const int tid = threadIdx.x;
    const int lane = tid & 31;
    const int warp = tid >> 5;
    const int g = lane >> 2;
    const int tig = lane & 3;
    const int wm = warp & 1;
    const int wn = warp >> 1;
    const int m0 = blockIdx.y * 128;
    const int n0 = blockIdx.x * 128;

    float acc[4][4][4];
#pragma unroll
    for (int i = 0; i < 4; i++)
#pragma unroll
        for (int j = 0; j < 4; j++)
#pragma unroll
            for (int e = 0; e < 4; e++) acc[i][j][e] = 0.0f;

    int lrow[4], lc[4];
#pragma unroll
    for (int p = 0; p < 4; p++) {
        int id = tid + p * 256;
        lrow[p] = id >> 3;
        lc[p] = (id & 7) * 4;
    }

    {
#pragma unroll
        for (int p = 0; p < 4; p++) {
            int r = lrow[p], kc = lc[p];
            float4 va = make_float4(0.f, 0.f, 0.f, 0.f);
            if (m0 + r < M) va = *(const float4*)(A + (size_t)(m0 + r) * 512 + kc);
            *(uint4*)(As + r * GSTR + kc) = *(const uint4*)&va;
            float4 vb = *(const float4*)(W + (size_t)(n0 + r) * 512 + kc);
            *(uint4*)(Bs + r * GSTR + kc) = *(const uint4*)&vb;
        }
    }
    __syncthreads();

    float4 pa[4], pb[4];
    for (int it = 0; it < 16; it++) {
        int buf = it & 1;
        if (it < 15) {
            int k0 = (it + 1) * 32;
#pragma unroll
            for (int p = 0; p < 4; p++) {
                int r = lrow[p], kc = lc[p];
                pa[p] = make_float4(0.f, 0.f, 0.f, 0.f);
                if (m0 + r < M) pa[p] = *(const float4*)(A + (size_t)(m0 + r) * 512 + k0 + kc);
                pb[p] = *(const float4*)(W + (size_t)(n0 + r) * 512 + k0 + kc);
            }
        }
        const unsigned* Ab = As + buf * GBUF;
        const unsigned* Bb = Bs + buf * GBUF;
#pragma unroll
        for (int kk = 0; kk < 4; kk++) {
            int kb = kk * 8;
            unsigned af[4][4];
#pragma unroll
            for (int mf = 0; mf < 4; mf++) {
                int r = wm * 64 + mf * 16 + g;
                af[mf][0] = Ab[r * GSTR + kb + tig];
                af[mf][1] = Ab[(r + 8) * GSTR + kb + tig];
                af[mf][2] = Ab[r * GSTR + kb + tig + 4];
                af[mf][3] = Ab[(r + 8) * GSTR + kb + tig + 4];
            }
            unsigned bf[4][2];
#pragma unroll
            for (int nf = 0; nf < 4; nf++) {
                int n = wn * 32 + nf * 8 + g;
                bf[nf][0] = Bb[n * GSTR + kb + tig];
                bf[nf][1] = Bb[n * GSTR + kb + tig + 4];
            }
#pragma unroll
            for (int mf = 0; mf < 4; mf++)
#pragma unroll
                for (int nf = 0; nf < 4; nf++)
                    mma_tf32(acc[mf][nf], af[mf], bf[nf]);
        }
        if (it < 15) {
            unsigned* Ad = As + (buf ^ 1) * GBUF;
            unsigned* Bd = Bs + (buf ^ 1) * GBUF;
#pragma unroll
            for (int p = 0; p < 4; p++) {
                int r = lrow[p], kc = lc[p];
                *(uint4*)(Ad + r * GSTR + kc) = *(const uint4*)&pa[p];
                *(uint4*)(Bd + r * GSTR + kc) = *(const uint4*)&pb[p];
            }
        }
        __syncthreads();
    }

#pragma unroll
    for (int nf = 0; nf < 4; nf++) {
        int n = n0 + wn * 32 + nf * 8 + 2 * tig;
        float bb0 = bi1[n] + bi2[n];
        float bb1 = bi1[n + 1] + bi2[n + 1];
#pragma unroll
        for (int mf = 0; mf < 4; mf++) {
            int r = m0 + wm * 64 + mf * 16 + g;
            if (r < M) {
                __half2 v = __floats2half2_rn(acc[mf][nf][0] + bb0, acc[mf][nf][1] + bb1);
                *(__half2*)(g_E0h + (size_t)r * G4 + n) = v;
            }
            if (r + 8 < M) {
                __half2 v = __floats2half2_rn(acc[mf][nf][2] + bb0, acc[mf][nf][3] + bb1);
                *(__half2*)(g_E0h + (size_t)(r + 8) * G4 + n) = v;
            }
        }
    }
}

// ---------------------------------------------------------------------------
// Fused two-layer pipelined LSTM scan, batch-split tiling, decoupled groups.
// 128 CTAs x 256 threads (1/SM). Block (ub = bid>>1, bh = bid&1) owns
// units [8ub, 8ub+8) (32 gate rows) x batches [32bh, 32bh+32).
// The two batch halves are COMPLETELY independent (own counter + bound).
// Warp w: ks = w>>1 (k-slice 128), ns = w&1 (rows ns*16+16).
// Post-staging sync is a PAIRWISE named barrier (warps 2ks,2ks+1 are the
// only producers+consumers of smem slice ks).
// E0 gather for step t+1 is prefetched between barrier arrive and poll.
// ---------------------------------------------------------------------------
__global__ __launch_bounds__(SCAN_THREADS) void lstm_fused_kernel(
    const int* __restrict__ src,
    const float* __restrict__ Whh0,
    const float* __restrict__ Wih1,
    const float* __restrict__ Whh1,
    const float* __restrict__ bih1,
    const float* __restrict__ bhh1,
    const int* __restrict__ sen_len,
    float* __restrict__ final_out)
{
    extern __shared__ unsigned ssm[];
    unsigned* sh_h0 = ssm;                     // 8192 u32 = 32 KB fp16 (this half)
    unsigned* sh_h1 = ssm + 8192;              // 8192 u32
    float* red0 = (float*)(ssm + 16384);       // [4][32][NPAD]
    float* red1 = red0 + 4 * 32 * NPAD;

    const int tid = threadIdx.x;
    const int lane = tid & 31;
    const int warp = tid >> 5;       // 0..7
    const int ks = warp >> 1;        // k-slice [128ks, 128ks+128)
    const int ns = warp & 1;         // row half
    const int g = lane >> 2;
    const int tig = lane & 3;
    const int ub = blockIdx.x >> 1;
    const int bh = blockIdx.x & 1;
    const int u0 = ub * 8;

    unsigned sh_base;
    asm("{ .reg .u64 t; cvta.to.shared.u64 t, %1; cvt.u32.u64 %0, t; }"
        : "=r"(sh_base) : "l"((void*)ssm));

    // ---- B fragments in registers (once): Whh0, Wih1, Whh1 ----
    unsigned breg0[8][2][2], bregI[8][2][2], bregU[8][2][2];
#pragma unroll
    for (int kkl = 0; kkl < 8; kkl++) {
#pragma unroll
        for (int nt = 0; nt < 2; nt++) {
            int n = ns * 16 + nt * 8 + g;
            size_t row = (size_t)((n & 3) * 512 + u0 + (n >> 2)) * 512
                       + ks * 128 + kkl * 16;
            {
                const float* wr = Whh0 + row;
                __half2 h0 = __floats2half2_rn(wr[2 * tig], wr[2 * tig + 1]);
                __half2 h1 = __floats2half2_rn(wr[2 * tig + 8], wr[2 * tig + 9]);
                breg0[kkl][nt][0] = *(unsigned*)&h0;
                breg0[kkl][nt][1] = *(unsigned*)&h1;
            }
            {
                const float* wr = Wih1 + row;
                __half2 h0 = __floats2half2_rn(wr[2 * tig], wr[2 * tig + 1]);
                __half2 h1 = __floats2half2_rn(wr[2 * tig + 8], wr[2 * tig + 9]);
                bregI[kkl][nt][0] = *(unsigned*)&h0;
                bregI[kkl][nt][1] = *(unsigned*)&h1;
            }
            {
                const float* wr = Whh1 + row;
                __half2 h0 = __floats2half2_rn(wr[2 * tig], wr[2 * tig + 1]);
                __half2 h1 = __floats2half2_rn(wr[2 * tig + 8], wr[2 * tig + 9]);
                bregU[kkl][nt][0] = *(unsigned*)&h0;
                bregU[kkl][nt][1] = *(unsigned*)&h1;
            }
        }
    }

    // ---- cell-phase mapping: thread = (unit u_loc, batch b_loc) ----
    const int u_loc = tid >> 5;          // 0..7
    const int b_loc = lane;              // 0..31
    const int b_glob = bh * 32 + b_loc;
    const int u_glob = u0 + u_loc;

    float bsum[4];
#pragma unroll
    for (int gt = 0; gt < 4; gt++)
        bsum[gt] = bih1[gt * 512 + u_glob] + bhh1[gt * 512 + u_glob];

    float c_l0 = 0.f, c_l1 = 0.f;
    const int sl = sen_len[b_glob];
    const int maxsl = g_maxsl2[bh];
    const int hi = hidx16(b_glob, u_glob);
    unsigned* ctr = &g_ctrs[bh][0];
    const int barid = 1 + ks;            // named barrier per warp pair

    // ---- initial E0 prefetch (t = 0) ----
    float p[4];
    {
        int r = src[b_glob];
        const __half* e = g_E0h + (size_t)r * G4 + u_glob;
#pragma unroll
        for (int gt = 0; gt < 4; gt++) p[gt] = __half2float(e[gt * 512]);
    }

    for (int t = 0; t <= maxsl; t++) {
        const bool do_l0 = (t < maxsl);
        const bool do_l1 = (t >= 1);

        // ---- stage: warp (ks,0) -> h0[t-1] slice; (ks,1) -> h1[t-2] slice ----
        {
            const uint4* gs = (const uint4*)(ns == 0 ? g_h0buf[(t + 1) & 1]
                                                     : g_h1buf[t & 1]);
            unsigned dstbase = sh_base + (ns ? 32768u : 0u);
#pragma unroll
            for (int i = 0; i < 16; i++) {
                int kk = ks * 8 + (i >> 1);
                int io = i & 1;
                int gidx = (kk * 4 + 2 * bh + io) * 32 + lane;
                int didx = (kk * 2 + io) * 32 + lane;
                cp16(dstbase + (unsigned)didx * 16, gs + gidx);
            }
            asm volatile("cp.async.commit_group;");
        }

        asm volatile("cp.async.wait_group 0;" ::: "memory");
        // pairwise sync: warps (ks,0),(ks,1) exchange their staged slices
        asm volatile("bar.sync %0, 64;" :: "r"(barid) : "memory");

        // ---- mma: 3 GEMMs, m32 x n16 x k128 per warp ----
        {
            float acc0[2][2][4], acc1[2][2][4];
#pragma unroll
            for (int mt2 = 0; mt2 < 2; mt2++)
#pragma unroll
                for (int nt = 0; nt < 2; nt++)
#pragma unroll
                    for (int e = 0; e < 4; e++) { acc0[mt2][nt][e] = 0.f; acc1[mt2][nt][e] = 0.f; }

#pragma unroll
            for (int kkl = 0; kkl < 8; kkl++) {
                int base = (ks * 8 + kkl) * 2;
#pragma unroll
                for (int mt2 = 0; mt2 < 2; mt2++) {
                    uint4 a0 = *(const uint4*)(sh_h0 + ((base + mt2) * 32 + lane) * 4);
                    mma_f16(acc0[mt2][0], (const unsigned*)&a0, breg0[kkl][0]);
                    mma_f16(acc0[mt2][1], (const unsigned*)&a0, breg0[kkl][1]);
                    mma_f16(acc1[mt2][0], (const unsigned*)&a0, bregI[kkl][0]);
                    mma_f16(acc1[mt2][1], (const unsigned*)&a0, bregI[kkl][1]);
                    uint4 a1 = *(const uint4*)(sh_h1 + ((base + mt2) * 32 + lane) * 4);
                    mma_f16(acc1[mt2][0], (const unsigned*)&a1, bregU[kkl][0]);
                    mma_f16(acc1[mt2][1], (const unsigned*)&a1, bregU[kkl][1]);
                }
            }

            // ---- store k-partials: red[ks][m_loc][n] ----
#pragma unroll
            for (int mt2 = 0; mt2 < 2; mt2++)
#pragma unroll
                for (int nt = 0; nt < 2; nt++) {
                    int m_loc = mt2 * 16 + g;
                    int col = ns * 16 + nt * 8 + 2 * tig;
                    float* rp0 = &red0[(ks * 32 + m_loc) * NPAD + col];
                    *(float2*)rp0 = make_float2(acc0[mt2][nt][0], acc0[mt2][nt][1]);
                    *(float2*)(rp0 + 8 * NPAD) = make_float2(acc0[mt2][nt][2], acc0[mt2][nt][3]);
                    float* rp1 = &red1[(ks * 32 + m_loc) * NPAD + col];
                    *(float2*)rp1 = make_float2(acc1[mt2][nt][0], acc1[mt2][nt][1]);
                    *(float2*)(rp1 + 8 * NPAD) = make_float2(acc1[mt2][nt][2], acc1[mt2][nt][3]);
                }
        }
        __syncthreads();

        // ---- layer0 cell: h_l0[t] ----
        if (do_l0) {
            float z[4];
#pragma unroll
            for (int gt = 0; gt < 4; gt++) z[gt] = p[gt];
#pragma unroll
            for (int w = 0; w < 4; w++) {
                float4 v = *(const float4*)&red0[(w * 32 + b_loc) * NPAD + u_loc * 4];
                z[0] += v.x; z[1] += v.y; z[2] += v.z; z[3] += v.w;
            }
            float ig = sig_(z[0]), fg = sig_(z[1]), gg = tanh_ap(z[2]), og = sig_(z[3]);
            c_l0 = fg * c_l0 + ig * gg;
            float hn = og * tanh_ap(c_l0);
            g_h0buf[t & 1][hi] = __float2half_rn(hn);
        }

        // ---- layer1 cell: h_l1[t-1] ----
        if (do_l1) {
            float z[4];
#pragma unroll
            for (int gt = 0; gt < 4; gt++) z[gt] = bsum[gt];
#pragma unroll
            for (int w = 0; w < 4; w++) {
                float4 v = *(const float4*)&red1[(w * 32 + b_loc) * NPAD + u_loc * 4];
                z[0] += v.x; z[1] += v.y; z[2] += v.z; z[3] += v.w;
            }
            float ig = sig_(z[0]), fg = sig_(z[1]), gg = tanh_ap(z[2]), og = sig_(z[3]);
            c_l1 = fg * c_l1 + ig * gg;
            float hn = og * tanh_ap(c_l1);
            g_h1buf[(t - 1) & 1][hi] = __float2half_rn(hn);
            if (t == sl) final_out[b_glob * HID + u_glob] = hn;
        }

        // ---- grid barrier (per-half counter) + E0 prefetch overlap ----
        __syncthreads();   // all h stores issued block-wide
        if (tid == 0) {
            asm volatile("red.release.gpu.global.add.u32 [%0], 1;"
                         :: "l"(ctr) : "memory");
        }
        // prefetch E0 for step t+1 while tid0 polls (independent of h)
        {
            int tt = (t + 1 < maxsl) ? (t + 1) : 0;
            int r = src[tt * NBATCH + b_glob];
            const __half* e = g_E0h + (size_t)r * G4 + u_glob;
#pragma unroll
            for (int gt = 0; gt < 4; gt++) p[gt] = __half2float(e[gt * 512]);
        }
        if (tid == 0) {
            unsigned tgt = 64u * (unsigned)(t + 1);
            while (ld_acq(ctr) < tgt) { }
        }
        __syncthreads();
    }
}

// ---------------------------------------------------------------------------
extern "C" void kernel_launch(void* const* d_in, const int* in_sizes, int n_in,
                              void* d_out, int out_size)
{
    const int*   src       = (const int*)  d_in[0];
    const int*   sen_len   = (const int*)  d_in[1];
    const float* emb_table = (const float*)d_in[2];
    const float* Wih0      = (const float*)d_in[3];
    const float* Whh0      = (const float*)d_in[4];
    const float* bih0      = (const float*)d_in[5];
    const float* bhh0      = (const float*)d_in[6];
    const float* Wih1      = (const float*)d_in[7];
    const float* Whh1      = (const float*)d_in[8];
    const float* bih1      = (const float*)d_in[9];
    const float* bhh1      = (const float*)d_in[10];
    float* out = (float*)d_out;

    const size_t gemm_smem = (size_t)4 * GBUF * sizeof(unsigned);        // 73728 B
    const size_t scan_smem =
        (size_t)(16384 + 2 * 4 * 32 * NPAD) * sizeof(unsigned);          // 102400 B
    cudaFuncSetAttribute(gemm_e0_kernel,
                         cudaFuncAttributeMaxDynamicSharedMemorySize, (int)gemm_smem);
    cudaFuncSetAttribute(lstm_fused_kernel,
                         cudaFuncAttributeMaxDynamicSharedMemorySize, (int)scan_smem);

    // Phase 0: E0 = emb_table @ Wih0^T + (bih0+bhh0)   (10000 x 2048, fp16)
    {
        dim3 grid(G4 / 128, (NVOCAB + 127) / 128);
        gemm_e0_kernel<<<grid, 256, gemm_smem>>>(emb_table, Wih0, bih0, bhh0, NVOCAB);
    }

    // Phase 1: fused two-layer pipelined scan, decoupled batch halves
    zero_init_kernel<<<128, 512>>>(sen_len);
    lstm_fused_kernel<<<SCAN_BLOCKS, SCAN_THREADS, scan_smem>>>(
        src, Whh0, Wih1, Whh1, bih1, bhh1, sen_len, out);
}